// round 6
// baseline (speedup 1.0000x reference)
#include <cuda_runtime.h>
#include <cstdint>

// Shapes (fixed)
#define BB   8
#define SS   512
#define MEM_ 512
#define LL   4
#define EE   512
#define HH   8
#define DH_  64
#define OBS_ 128
#define KK   1024   // MEM + S
#define LW   (EE*EE)

// ---------------- scratch (static device globals) -----------------------------
__device__ float g_x [BB*SS*EE];
__device__ float g_h [BB*SS*EE];
__device__ float g_hn[BB*SS*EE];
__device__ float g_t [BB*SS*EE];
__device__ float g_vk[BB*KK*EE];
__device__ float g_q [BB*SS*EE];
__device__ float g_k [BB*KK*EE];
__device__ float g_v [BB*KK*EE];
__device__ float g_o [BB*SS*EE];
__device__ float g_r [KK*EE];
__device__ float g_pe[KK*EE];
__device__ float g_sc[(long)BB*HH*SS*KK];   // AC scores
__device__ float g_P [(long)BB*HH*SS*KK];   // rel-position term

// ---------------- helpers ------------------------------------------------------
__device__ __forceinline__ uint32_t f2tf32(float x) {
    uint32_t o;
    asm("cvt.rna.tf32.f32 %0, %1;" : "=r"(o) : "f"(x));
    return o;
}
__device__ __forceinline__ void mma_tf32(float* d, const uint32_t* a, const uint32_t* b) {
    asm volatile(
        "mma.sync.aligned.m16n8k8.row.col.f32.tf32.tf32.f32 "
        "{%0,%1,%2,%3}, {%4,%5,%6,%7}, {%8,%9}, {%0,%1,%2,%3};"
        : "+f"(d[0]), "+f"(d[1]), "+f"(d[2]), "+f"(d[3])
        : "r"(a[0]), "r"(a[1]), "r"(a[2]), "r"(a[3]), "r"(b[0]), "r"(b[1]));
}
__device__ __forceinline__ float gelu_f(float x) {
    return 0.5f * x * (1.0f + tanhf(0.7978845608028654f * (x + 0.044715f * x * x * x)));
}

// ---------------- unified tf32 mma.sync GEMM -----------------------------------
// (validated in R4; layouts unchanged)
#define AS_STRIDE 36
#define BS_STRIDE 72
#define A_BUF (128 * AS_STRIDE)
#define B_BUF (32 * BS_STRIDE)
#define SMEM_FLOATS (2 * (A_BUF + B_BUF))

template<int EPI, bool BTR, bool AADD>
__global__ __launch_bounds__(256)
void mma_gemm(const float* __restrict__ A, long a_o, long a_i, int lda,
              const float* __restrict__ B, long b_o, long b_i, int ldb,
              float* __restrict__ C, long c_o, long c_i, int ldc,
              const float* __restrict__ bias, const float* __restrict__ resid,
              const float* __restrict__ addv, int Hd, int Kd) {
    extern __shared__ float smem[];
    float* sA = smem;
    float* sB = smem + 2 * A_BUF;

    const int tid = threadIdx.x;
    const int z = blockIdx.z;
    const int m0 = blockIdx.y * 128;
    const int n0 = blockIdx.x * 64;

    const long aoff = ((long)(z / Hd)) * a_o + (long)(z % Hd) * a_i;
    const long boff = ((long)(z / Hd)) * b_o + (long)(z % Hd) * b_i;
    const long coff = ((long)(z / Hd)) * c_o + (long)(z % Hd) * c_i;
    const float* Ap = A + aoff + (long)m0 * lda;
    const float* Bp = B + boff + (BTR ? (long)n0 * ldb : (long)n0);
    const float* av = AADD ? (addv + (z % Hd) * DH_) : nullptr;

    const int lane = tid & 31, w = tid >> 5;
    const int g = lane >> 2, t4 = lane & 3;
    const int m_base = (w & 3) * 32;
    const int n_base = (w >> 2) * 32;

    float ra[16], rb[8];

    auto fetch = [&](int c) {
#pragma unroll
        for (int i = 0; i < 4; i++) {
            int q = tid + i * 256;
            int row = q >> 3, c4 = q & 7;
            float4 v = *(const float4*)(Ap + (long)row * lda + c * 32 + c4 * 4);
            if (AADD) {
                float4 a4 = *(const float4*)(av + c * 32 + c4 * 4);
                v.x = (v.x + a4.x) * 0.125f; v.y = (v.y + a4.y) * 0.125f;
                v.z = (v.z + a4.z) * 0.125f; v.w = (v.w + a4.w) * 0.125f;
            }
            ra[i*4+0] = v.x; ra[i*4+1] = v.y; ra[i*4+2] = v.z; ra[i*4+3] = v.w;
        }
#pragma unroll
        for (int i = 0; i < 2; i++) {
            int q = tid + i * 256;
            float4 v;
            if (!BTR) {
                int row = q >> 4, c4 = q & 15;
                v = *(const float4*)(Bp + (long)(c * 32 + row) * ldb + c4 * 4);
            } else {
                int nn = q >> 3, kc4 = q & 7;
                v = *(const float4*)(Bp + (long)nn * ldb + c * 32 + kc4 * 4);
            }
            rb[i*4+0] = v.x; rb[i*4+1] = v.y; rb[i*4+2] = v.z; rb[i*4+3] = v.w;
        }
    };
    auto stage = [&](int bf) {
        float* dA = sA + bf * A_BUF;
        float* dB = sB + bf * B_BUF;
#pragma unroll
        for (int i = 0; i < 4; i++) {
            int q = tid + i * 256;
            int row = q >> 3, c4 = q & 7;
            uint32_t* d = (uint32_t*)(dA + row * AS_STRIDE + c4 * 4);
            d[0] = f2tf32(ra[i*4+0]); d[1] = f2tf32(ra[i*4+1]);
            d[2] = f2tf32(ra[i*4+2]); d[3] = f2tf32(ra[i*4+3]);
        }
#pragma unroll
        for (int i = 0; i < 2; i++) {
            int q = tid + i * 256;
            if (!BTR) {
                int row = q >> 4, c4 = q & 15;
                uint32_t* d = (uint32_t*)(dB + row * BS_STRIDE + c4 * 4);
                d[0] = f2tf32(rb[i*4+0]); d[1] = f2tf32(rb[i*4+1]);
                d[2] = f2tf32(rb[i*4+2]); d[3] = f2tf32(rb[i*4+3]);
            } else {
                int nn = q >> 3, kc4 = q & 7;
#pragma unroll
                for (int j = 0; j < 4; j++)
                    *(uint32_t*)(dB + (kc4 * 4 + j) * BS_STRIDE + nn) = f2tf32(rb[i*4+j]);
            }
        }
    };

    float acc[2][4][4] = {};
    const int nch = Kd / 32;

    fetch(0); stage(0);
    __syncthreads();

    for (int c = 0; c < nch; c++) {
        const int bf = c & 1;
        if (c + 1 < nch) fetch(c + 1);

        const float* cA = sA + bf * A_BUF;
        const float* cB = sB + bf * B_BUF;
#pragma unroll
        for (int ks = 0; ks < 4; ks++) {
            const int k = ks * 8;
            uint32_t af[2][4], bfr[4][2];
#pragma unroll
            for (int mt = 0; mt < 2; mt++) {
                const float* p = cA + (m_base + mt * 16 + g) * AS_STRIDE + k + t4;
                af[mt][0] = __float_as_uint(p[0]);
                af[mt][1] = __float_as_uint(p[8 * AS_STRIDE]);
                af[mt][2] = __float_as_uint(p[4]);
                af[mt][3] = __float_as_uint(p[8 * AS_STRIDE + 4]);
            }
#pragma unroll
            for (int nt = 0; nt < 4; nt++) {
                const float* p = cB + (k + t4) * BS_STRIDE + n_base + nt * 8 + g;
                bfr[nt][0] = __float_as_uint(p[0]);
                bfr[nt][1] = __float_as_uint(p[4 * BS_STRIDE]);
            }
#pragma unroll
            for (int mt = 0; mt < 2; mt++)
#pragma unroll
                for (int nt = 0; nt < 4; nt++)
                    mma_tf32(acc[mt][nt], af[mt], bfr[nt]);
        }
        if (c + 1 < nch) stage((c + 1) & 1);
        __syncthreads();
    }

#pragma unroll
    for (int mt = 0; mt < 2; mt++) {
#pragma unroll
        for (int half = 0; half < 2; half++) {
            const int row = m0 + m_base + mt * 16 + g + half * 8;
            float* Cr = C + coff + (long)row * ldc + n0;
            const float* Rr = (EPI == 3) ? (resid + coff + (long)row * ldc + n0) : nullptr;
#pragma unroll
            for (int nt = 0; nt < 4; nt++) {
                const int cn = n_base + nt * 8 + t4 * 2;
                float2 o;
                o.x = acc[mt][nt][half * 2 + 0];
                o.y = acc[mt][nt][half * 2 + 1];
                if (EPI >= 1) {
                    float2 b2 = *(const float2*)(bias + n0 + cn);
                    o.x += b2.x; o.y += b2.y;
                }
                if (EPI == 2) { o.x = gelu_f(o.x); o.y = gelu_f(o.y); }
                if (EPI == 3) {
                    float2 r2 = *(const float2*)(Rr + cn);
                    o.x += r2.x; o.y += r2.y;
                }
                *(float2*)(Cr + cn) = o;
            }
        }
    }
}

// ---------------- fused flash AV: softmax(AC + shift(P)) @ V -------------------
// Block: 128 q-rows x one (b,h). Online softmax over K chunks of 64.
// Score/P loads are lane-contiguous in j (full 128B sectors).
#define SP_ST 68
#define SV_ST 72
#define FL_SMEM ((128*SP_ST + 64*SV_ST + 256) * 4)

__global__ __launch_bounds__(256)
void flash_av(const float* __restrict__ sc, const float* __restrict__ P,
              const float* __restrict__ v, float* __restrict__ o) {
    extern __shared__ float fs[];
    float* sp     = fs;                       // [128][SP_ST]
    float* sv     = fs + 128 * SP_ST;         // [64][SV_ST]
    float* s_corr = sv + 64 * SV_ST;          // [128]
    float* s_linv = s_corr + 128;             // [128]

    const int tid = threadIdx.x;
    const int i0 = blockIdx.x * 128;
    const int z = blockIdx.y;
    const int b = z >> 3, h = z & 7;

    const float* scb = sc + ((long)z * SS + i0) * KK;
    const float* Pb  = P  + ((long)z * SS) * KK;
    const float* vb  = v + (long)b * KK * EE + h * DH_;

    const int srow = tid >> 1;                // softmax: 2 threads/row
    const int shalf = tid & 1;
    float m_r = -1e30f, l_r = 0.f;

    const int lane = tid & 31, w = tid >> 5;
    const int g = lane >> 2, t4 = lane & 3;
    const int wm = (w & 3) * 32, wn = (w >> 2) * 32;
    float acc[2][4][4] = {};

    const int nch = (MEM_ + i0 + 128) / 64;
    for (int c = 0; c < nch; c++) {
        const int j0 = c * 64;
        // ---- coalesced load: s = AC + gathered P, masked ----
        // idx linear over 128 rows x 64 cols: lanes cover consecutive j.
#pragma unroll
        for (int it = 0; it < 32; it++) {
            int idx = tid + it * 256;
            int row = idx >> 6, j = idx & 63;
            int ia = i0 + row;
            int jlim = MEM_ + ia - j0;
            float x = -1e30f;
            if (j <= jlim)
                x = scb[(long)row * KK + j0 + j]
                  + Pb[(long)ia * KK + (SS - 1 - ia) + j0 + j];
            sp[row * SP_ST + j] = x;
        }
        // ---- load v chunk (tf32) ----
#pragma unroll
        for (int ii = 0; ii < 4; ii++) {
            int q = tid + ii * 256;
            int kr = q >> 4, c4 = (q & 15) * 4;
            float4 vv = *(const float4*)(vb + (long)(j0 + kr) * EE + c4);
            uint32_t* d = (uint32_t*)(sv + kr * SV_ST + c4);
            d[0] = f2tf32(vv.x); d[1] = f2tf32(vv.y);
            d[2] = f2tf32(vv.z); d[3] = f2tf32(vv.w);
        }
        __syncthreads();
        // ---- online softmax stats, overwrite sp with tf32 probs ----
        {
            float* row = sp + srow * SP_ST;
            float vals[32];
            float mx = -1e30f;
#pragma unroll
            for (int ii = 0; ii < 32; ii++) {
                vals[ii] = row[shalf + 2 * ii];
                mx = fmaxf(mx, vals[ii]);
            }
            mx = fmaxf(mx, __shfl_xor_sync(0xffffffffu, mx, 1));
            float m_new = fmaxf(m_r, mx);
            float corr = __expf(m_r - m_new);
            float sum = 0.f;
#pragma unroll
            for (int ii = 0; ii < 32; ii++) {
                float e = __expf(vals[ii] - m_new);
                sum += e;
                row[shalf + 2 * ii] = __uint_as_float(f2tf32(e));
            }
            sum += __shfl_xor_sync(0xffffffffu, sum, 1);
            l_r = l_r * corr + sum;
            m_r = m_new;
            if (shalf == 0) s_corr[srow] = corr;
        }
        __syncthreads();
        // ---- rescale acc, then probs @ v via mma ----
#pragma unroll
        for (int mt = 0; mt < 2; mt++) {
            float c0 = s_corr[wm + mt * 16 + g];
            float c1 = s_corr[wm + mt * 16 + g + 8];
#pragma unroll
            for (int nt = 0; nt < 4; nt++) {
                acc[mt][nt][0] *= c0; acc[mt][nt][1] *= c0;
                acc[mt][nt][2] *= c1; acc[mt][nt][3] *= c1;
            }
        }
#pragma unroll
        for (int ks = 0; ks < 8; ks++) {
            const int k = ks * 8;
            uint32_t af[2][4], bfr[4][2];
#pragma unroll
            for (int mt = 0; mt < 2; mt++) {
                const float* p = sp + (wm + mt * 16 + g) * SP_ST + k + t4;
                af[mt][0] = __float_as_uint(p[0]);
                af[mt][1] = __float_as_uint(p[8 * SP_ST]);
                af[mt][2] = __float_as_uint(p[4]);
                af[mt][3] = __float_as_uint(p[8 * SP_ST + 4]);
            }
#pragma unroll
            for (int nt = 0; nt < 4; nt++) {
                const float* p = sv + (k + t4) * SV_ST + wn + nt * 8 + g;
                bfr[nt][0] = __float_as_uint(p[0]);
                bfr[nt][1] = __float_as_uint(p[4 * SV_ST]);
            }
#pragma unroll
            for (int mt = 0; mt < 2; mt++)
#pragma unroll
                for (int nt = 0; nt < 4; nt++)
                    mma_tf32(acc[mt][nt], af[mt], bfr[nt]);
        }
        __syncthreads();
    }
    // ---- finalize ----
    if (shalf == 0) s_linv[srow] = 1.f / l_r;
    __syncthreads();
    float* ob = o + (long)(b * SS + i0) * EE + h * DH_;
#pragma unroll
    for (int mt = 0; mt < 2; mt++) {
#pragma unroll
        for (int half = 0; half < 2; half++) {
            const int row = wm + mt * 16 + g + half * 8;
            const float li = s_linv[row];
            float* orow = ob + (long)row * EE + wn;
#pragma unroll
            for (int nt = 0; nt < 4; nt++) {
                float2 t;
                t.x = acc[mt][nt][half * 2 + 0] * li;
                t.y = acc[mt][nt][half * 2 + 1] * li;
                *(float2*)(orow + nt * 8 + t4 * 2) = t;
            }
        }
    }
}

// ---------------- positional embedding ----------------------------------------
__global__ void pe_kernel(float* __restrict__ pe) {
    int idx = blockIdx.x * 256 + threadIdx.x;
    int m = idx >> 9, c = idx & 511;
    double pos  = (double)(KK - m);
    int    t2   = c & 255;
    double invf = exp(-((double)(2 * t2) / 512.0) * log(10000.0));
    double a    = pos * invf;
    pe[idx] = (float)((c < 256) ? sin(a) : cos(a));
}

// ---------------- layer norm ---------------------------------------------------
__device__ __forceinline__ void ln_row(const float* __restrict__ src,
                                       float* __restrict__ dst,
                                       const float* __restrict__ g,
                                       const float* __restrict__ be, int lane) {
    float4 vals[4];
    float s = 0.f, ss = 0.f;
#pragma unroll
    for (int t = 0; t < 4; t++) {
        vals[t] = *(const float4*)(src + lane * 4 + t * 128);
        s  += vals[t].x + vals[t].y + vals[t].z + vals[t].w;
        ss += vals[t].x*vals[t].x + vals[t].y*vals[t].y
            + vals[t].z*vals[t].z + vals[t].w*vals[t].w;
    }
#pragma unroll
    for (int o = 16; o; o >>= 1) {
        s  += __shfl_xor_sync(0xffffffffu, s,  o);
        ss += __shfl_xor_sync(0xffffffffu, ss, o);
    }
    float mean = s * (1.f / 512.f);
    float var  = ss * (1.f / 512.f) - mean * mean;
    float rstd = rsqrtf(var + 1e-6f);
#pragma unroll
    for (int t = 0; t < 4; t++) {
        int e = lane * 4 + t * 128;
        float4 o4;
        o4.x = (vals[t].x - mean) * rstd * g[e+0] + be[e+0];
        o4.y = (vals[t].y - mean) * rstd * g[e+1] + be[e+1];
        o4.z = (vals[t].z - mean) * rstd * g[e+2] + be[e+2];
        o4.w = (vals[t].w - mean) * rstd * g[e+3] + be[e+3];
        *(float4*)(dst + e) = o4;
    }
}

__global__ void ln_concat_k(const float* __restrict__ mem, const float* __restrict__ x,
                            const float* __restrict__ gam, const float* __restrict__ bet,
                            float* __restrict__ out, int l) {
    int row  = blockIdx.x * 8 + (threadIdx.x >> 5);
    int lane = threadIdx.x & 31;
    int b = row >> 10, j = row & 1023;
    const float* src = (j < MEM_)
        ? (mem + ((long)(b * MEM_ + j) * LL + l) * EE)
        : (x   +  (long)(b * SS + (j - MEM_)) * EE);
    ln_row(src, out + (long)row * EE, gam + l * EE, bet + l * EE, lane);
}

__global__ void ln_plain_k(const float* __restrict__ in,
                           const float* __restrict__ gam, const float* __restrict__ bet,
                           float* __restrict__ out, int l) {
    int row  = blockIdx.x * 8 + (threadIdx.x >> 5);
    int lane = threadIdx.x & 31;
    ln_row(in + (long)row * EE, out + (long)row * EE, gam + l * EE, bet + l * EE, lane);
}

// ---------------- host orchestration ------------------------------------------
#define SMEM_BYTES (SMEM_FLOATS * 4)

extern "C" void kernel_launch(void* const* d_in, const int* in_sizes, int n_in,
                              void* d_out, int out_size) {
    (void)in_sizes; (void)n_in; (void)out_size;
    const float* obs    = (const float*)d_in[0];
    const float* mems   = (const float*)d_in[1];
    const float* W_enc  = (const float*)d_in[3];
    const float* b_enc  = (const float*)d_in[4];
    const float* ln1_s  = (const float*)d_in[5];
    const float* ln1_b  = (const float*)d_in[6];
    const float* Wq     = (const float*)d_in[7];
    const float* bq     = (const float*)d_in[8];
    const float* Wk     = (const float*)d_in[9];
    const float* bk     = (const float*)d_in[10];
    const float* Wv     = (const float*)d_in[11];
    const float* bv     = (const float*)d_in[12];
    const float* Wr     = (const float*)d_in[13];
    const float* ub     = (const float*)d_in[14];
    const float* vbias  = (const float*)d_in[15];
    const float* Wo     = (const float*)d_in[16];
    const float* bo     = (const float*)d_in[17];
    const float* ln2_s  = (const float*)d_in[18];
    const float* ln2_b  = (const float*)d_in[19];
    const float* W1     = (const float*)d_in[20];
    const float* b1     = (const float*)d_in[21];
    const float* W2     = (const float*)d_in[22];
    const float* b2     = (const float*)d_in[23];
    float* out = (float*)d_out;

    float *px, *ph, *phn, *pt, *pvk, *pq, *pk, *pv_, *po, *pr, *ppe, *psc, *pP;
    cudaGetSymbolAddress((void**)&px,  g_x);
    cudaGetSymbolAddress((void**)&ph,  g_h);
    cudaGetSymbolAddress((void**)&phn, g_hn);
    cudaGetSymbolAddress((void**)&pt,  g_t);
    cudaGetSymbolAddress((void**)&pvk, g_vk);
    cudaGetSymbolAddress((void**)&pq,  g_q);
    cudaGetSymbolAddress((void**)&pk,  g_k);
    cudaGetSymbolAddress((void**)&pv_, g_v);
    cudaGetSymbolAddress((void**)&po,  g_o);
    cudaGetSymbolAddress((void**)&pr,  g_r);
    cudaGetSymbolAddress((void**)&ppe, g_pe);
    cudaGetSymbolAddress((void**)&psc, g_sc);
    cudaGetSymbolAddress((void**)&pP,  g_P);

    cudaFuncSetAttribute(mma_gemm<1,false,false>, cudaFuncAttributeMaxDynamicSharedMemorySize, SMEM_BYTES);
    cudaFuncSetAttribute(mma_gemm<0,false,false>, cudaFuncAttributeMaxDynamicSharedMemorySize, SMEM_BYTES);
    cudaFuncSetAttribute(mma_gemm<0,true ,true >, cudaFuncAttributeMaxDynamicSharedMemorySize, SMEM_BYTES);
    cudaFuncSetAttribute(mma_gemm<2,false,false>, cudaFuncAttributeMaxDynamicSharedMemorySize, SMEM_BYTES);
    cudaFuncSetAttribute(mma_gemm<3,false,false>, cudaFuncAttributeMaxDynamicSharedMemorySize, SMEM_BYTES);
    cudaFuncSetAttribute(flash_av, cudaFuncAttributeMaxDynamicSharedMemorySize, FL_SMEM);

    const long SE = (long)SS * EE, KE = (long)KK * EE, SK = (long)SS * KK;
    const long HSK = (long)HH * SK;

    // encoder: x = obs @ W_enc + b_enc
    mma_gemm<1,false,false><<<dim3(8, 32, 1), 256, SMEM_BYTES>>>(
        obs, 0, 0, OBS_, W_enc, 0, 0, EE, px, 0, 0, EE,
        b_enc, nullptr, nullptr, 1, OBS_);
    pe_kernel<<<(KK * EE) / 256, 256>>>(ppe);

    for (int l = 0; l < LL; l++) {
        ln_concat_k<<<(BB * KK) / 8, 256>>>(mems, px, ln1_s, ln1_b, pvk, l);

        mma_gemm<1,false,false><<<dim3(8, 64, 1), 256, SMEM_BYTES>>>(
            pvk, 0, 0, EE, Wk + (long)l * LW, 0, 0, EE, pk, 0, 0, EE,
            bk + l * EE, nullptr, nullptr, 1, EE);
        mma_gemm<1,false,false><<<dim3(8, 64, 1), 256, SMEM_BYTES>>>(
            pvk, 0, 0, EE, Wv + (long)l * LW, 0, 0, EE, pv_, 0, 0, EE,
            bv + l * EE, nullptr, nullptr, 1, EE);
        mma_gemm<1,false,false><<<dim3(8, 4, BB), 256, SMEM_BYTES>>>(
            pvk + (long)MEM_ * EE, KE, 0, EE, Wq + (long)l * LW, 0, 0, EE,
            pq, SE, 0, EE, bq + l * EE, nullptr, nullptr, 1, EE);
        mma_gemm<0,false,false><<<dim3(8, 8, 1), 256, SMEM_BYTES>>>(
            ppe, 0, 0, EE, Wr + (long)l * LW, 0, 0, EE, pr, 0, 0, EE,
            nullptr, nullptr, nullptr, 1, EE);

        // AC = ((q+u)*0.125) @ k^T
        mma_gemm<0,true,true><<<dim3(16, 4, BB*HH), 256, SMEM_BYTES>>>(
            pq, SE, DH_, EE, pk, KE, DH_, EE, psc, HSK, SK, KK,
            nullptr, nullptr, ub + (long)l * EE, HH, DH_);
        // P = ((q+v)*0.125) @ r^T
        mma_gemm<0,true,true><<<dim3(16, 4, BB*HH), 256, SMEM_BYTES>>>(
            pq, SE, DH_, EE, pr, 0, DH_, EE, pP, HSK, SK, KK,
            nullptr, nullptr, vbias + (long)l * EE, HH, DH_);

        // fused: softmax(AC + shift(P), mask) @ V
        flash_av<<<dim3(SS / 128, BB * HH), 256, FL_SMEM>>>(psc, pP, pv_, po);

        mma_gemm<3,false,false><<<dim3(8, 32, 1), 256, SMEM_BYTES>>>(
            po, 0, 0, EE, Wo + (long)l * LW, 0, 0, EE, ph, 0, 0, EE,
            bo + l * EE, px, nullptr, 1, EE);
        ln_plain_k<<<(BB * SS) / 8, 256>>>(ph, ln2_s, ln2_b, phn, l);
        mma_gemm<2,false,false><<<dim3(8, 32, 1), 256, SMEM_BYTES>>>(
            phn, 0, 0, EE, W1 + (long)l * LW, 0, 0, EE, pt, 0, 0, EE,
            b1 + l * EE, nullptr, nullptr, 1, EE);
        float* xo = (l == LL - 1) ? out : px;
        mma_gemm<3,false,false><<<dim3(8, 32, 1), 256, SMEM_BYTES>>>(
            pt, 0, 0, EE, W2 + (long)l * LW, 0, 0, EE, xo, 0, 0, EE,
            b2 + l * EE, ph, nullptr, 1, EE);
    }
}

// round 7
// speedup vs baseline: 1.7435x; 1.7435x over previous
#include <cuda_runtime.h>
#include <cstdint>

// Shapes (fixed)
#define BB   8
#define SS   512
#define MEM_ 512
#define LL   4
#define EE   512
#define HH   8
#define DH_  64
#define OBS_ 128
#define KK   1024   // MEM + S
#define LW   (EE*EE)

// ---------------- scratch (static device globals) -----------------------------
__device__ float g_x [BB*SS*EE];
__device__ float g_h [BB*SS*EE];
__device__ float g_hn[BB*SS*EE];
__device__ float g_t [BB*SS*EE];
__device__ float g_vk[BB*KK*EE];
__device__ float g_q [BB*SS*EE];
__device__ float g_k [BB*KK*EE];
__device__ float g_v [BB*KK*EE];
__device__ float g_o [BB*SS*EE];
__device__ float g_r [KK*EE];
__device__ float g_pe[KK*EE];
__device__ float g_sc[(long)BB*HH*SS*KK];   // scores / probs (in-place)
__device__ float g_P [(long)BB*HH*SS*KK];   // rel-position term

// ---------------- helpers ------------------------------------------------------
__device__ __forceinline__ uint32_t f2tf32(float x) {
    uint32_t o;
    asm("cvt.rna.tf32.f32 %0, %1;" : "=r"(o) : "f"(x));
    return o;
}
__device__ __forceinline__ uint32_t smem_u32(const void* p) {
    uint32_t a;
    asm("{ .reg .u64 t; cvta.to.shared.u64 t, %1; cvt.u32.u64 %0, t; }"
        : "=r"(a) : "l"(p));
    return a;
}
__device__ __forceinline__ void cp_async16(uint32_t dst, const void* src) {
    asm volatile("cp.async.cg.shared.global [%0], [%1], 16;"
                 :: "r"(dst), "l"(src) : "memory");
}
__device__ __forceinline__ void cp_commit() {
    asm volatile("cp.async.commit_group;" ::: "memory");
}
__device__ __forceinline__ void cp_wait1() {
    asm volatile("cp.async.wait_group 1;" ::: "memory");
}
__device__ __forceinline__ void mma_tf32(float* d, const uint32_t* a, const uint32_t* b) {
    asm volatile(
        "mma.sync.aligned.m16n8k8.row.col.f32.tf32.tf32.f32 "
        "{%0,%1,%2,%3}, {%4,%5,%6,%7}, {%8,%9}, {%0,%1,%2,%3};"
        : "+f"(d[0]), "+f"(d[1]), "+f"(d[2]), "+f"(d[3])
        : "r"(a[0]), "r"(a[1]), "r"(a[2]), "r"(a[3]), "r"(b[0]), "r"(b[1]));
}
__device__ __forceinline__ float gelu_f(float x) {
    return 0.5f * x * (1.0f + tanhf(0.7978845608028654f * (x + 0.044715f * x * x * x)));
}

#define AS_STRIDE 36
#define BS_STRIDE 72
#define A_BUF (128 * AS_STRIDE)
#define B_BUF (32 * BS_STRIDE)

// ---------------- cp.async pipelined tf32 GEMM (BTR=false, no AADD) ------------
// C[z][m,n] = A[z][m,:] @ B[z][:,n], tile 128x64, BK=32, 3-stage cp.async.
// A raw fp32 in smem; cvt.rna.tf32 applied at fragment read.
#define PIPE 3
#define STAGE_FLOATS (A_BUF + B_BUF)
#define CA_SMEM_BYTES (PIPE * STAGE_FLOATS * 4)

template<int EPI>
__global__ __launch_bounds__(256)
void mma_gemm_ca(const float* __restrict__ A, long a_o, long a_i, int lda,
                 const float* __restrict__ B, long b_o, long b_i, int ldb,
                 float* __restrict__ C, long c_o, long c_i, int ldc,
                 const float* __restrict__ bias, const float* __restrict__ resid,
                 int Hd, int Kd) {
    extern __shared__ float smem[];
    const uint32_t sbase = smem_u32(smem);

    const int tid = threadIdx.x;
    const int z = blockIdx.z;
    const int m0 = blockIdx.y * 128;
    const int n0 = blockIdx.x * 64;

    const long aoff = ((long)(z / Hd)) * a_o + (long)(z % Hd) * a_i;
    const long boff = ((long)(z / Hd)) * b_o + (long)(z % Hd) * b_i;
    const long coff = ((long)(z / Hd)) * c_o + (long)(z % Hd) * c_i;
    const float* Ap = A + aoff + (long)m0 * lda;
    const float* Bp = B + boff + (long)n0;

    const int lane = tid & 31, w = tid >> 5;
    const int g = lane >> 2, t4 = lane & 3;
    const int m_base = (w & 3) * 32;
    const int n_base = (w >> 2) * 32;

    const int a_row = tid >> 3, a_c4 = (tid & 7) * 4;      // A: 4 iters stride 32 rows
    const int b_kr = tid >> 4, b_c4 = (tid & 15) * 4;      // B: 2 iters stride 16 rows

    auto issue_stage = [&](int c, int s) {
        uint32_t sa = sbase + (uint32_t)(s * STAGE_FLOATS) * 4u;
        uint32_t sb = sa + (uint32_t)A_BUF * 4u;
#pragma unroll
        for (int i = 0; i < 4; i++) {
            int row = a_row + i * 32;
            cp_async16(sa + (uint32_t)(row * AS_STRIDE + a_c4) * 4u,
                       Ap + (long)row * lda + c * 32 + a_c4);
        }
#pragma unroll
        for (int i = 0; i < 2; i++) {
            int kr = b_kr + i * 16;
            cp_async16(sb + (uint32_t)(kr * BS_STRIDE + b_c4) * 4u,
                       Bp + (long)(c * 32 + kr) * ldb + b_c4);
        }
    };

    const int nch = Kd / 32;
    // prologue: stages 0..PIPE-2
#pragma unroll
    for (int s = 0; s < PIPE - 1; s++) {
        if (s < nch) issue_stage(s, s);
        cp_commit();
    }

    float acc[2][4][4] = {};

    for (int c = 0; c < nch; c++) {
        cp_wait1();              // group for stage c complete
        __syncthreads();

        const float* cA = smem + (c % PIPE) * STAGE_FLOATS;
        const float* cB = cA + A_BUF;
#pragma unroll
        for (int ks = 0; ks < 4; ks++) {
            const int k = ks * 8;
            uint32_t af[2][4], bfr[4][2];
#pragma unroll
            for (int mt = 0; mt < 2; mt++) {
                const float* p = cA + (m_base + mt * 16 + g) * AS_STRIDE + k + t4;
                af[mt][0] = f2tf32(p[0]);
                af[mt][1] = f2tf32(p[8 * AS_STRIDE]);
                af[mt][2] = f2tf32(p[4]);
                af[mt][3] = f2tf32(p[8 * AS_STRIDE + 4]);
            }
#pragma unroll
            for (int nt = 0; nt < 4; nt++) {
                const float* p = cB + (k + t4) * BS_STRIDE + n_base + nt * 8 + g;
                bfr[nt][0] = f2tf32(p[0]);
                bfr[nt][1] = f2tf32(p[4 * BS_STRIDE]);
            }
#pragma unroll
            for (int mt = 0; mt < 2; mt++)
#pragma unroll
                for (int nt = 0; nt < 4; nt++)
                    mma_tf32(acc[mt][nt], af[mt], bfr[nt]);
        }
        __syncthreads();         // all threads done with stage c before reuse
        if (c + PIPE - 1 < nch) issue_stage(c + PIPE - 1, (c + PIPE - 1) % PIPE);
        cp_commit();             // always commit (empty groups complete instantly)
    }

    // ---- epilogue ----
#pragma unroll
    for (int mt = 0; mt < 2; mt++) {
#pragma unroll
        for (int half = 0; half < 2; half++) {
            const int row = m0 + m_base + mt * 16 + g + half * 8;
            float* Cr = C + coff + (long)row * ldc + n0;
            const float* Rr = (EPI == 3) ? (resid + coff + (long)row * ldc + n0) : nullptr;
#pragma unroll
            for (int nt = 0; nt < 4; nt++) {
                const int cn = n_base + nt * 8 + t4 * 2;
                float2 o;
                o.x = acc[mt][nt][half * 2 + 0];
                o.y = acc[mt][nt][half * 2 + 1];
                if (EPI >= 1) {
                    float2 b2 = *(const float2*)(bias + n0 + cn);
                    o.x += b2.x; o.y += b2.y;
                }
                if (EPI == 2) { o.x = gelu_f(o.x); o.y = gelu_f(o.y); }
                if (EPI == 3) {
                    float2 r2 = *(const float2*)(Rr + cn);
                    o.x += r2.x; o.y += r2.y;
                }
                *(float2*)(Cr + cn) = o;
            }
        }
    }
}

// ---------------- original register-prefetch GEMM (AC/P path: BTR+AADD) -------
#define SMEM_FLOATS (2 * (A_BUF + B_BUF))
#define SMEM_BYTES (SMEM_FLOATS * 4)

__global__ __launch_bounds__(256)
void mma_gemm_sc(const float* __restrict__ A, long a_o, long a_i, int lda,
                 const float* __restrict__ B, long b_o, long b_i, int ldb,
                 float* __restrict__ C, long c_o, long c_i, int ldc,
                 const float* __restrict__ addv, int Hd, int Kd) {
    extern __shared__ float smem[];
    float* sA = smem;
    float* sB = smem + 2 * A_BUF;

    const int tid = threadIdx.x;
    const int z = blockIdx.z;
    const int m0 = blockIdx.y * 128;
    const int n0 = blockIdx.x * 64;

    const long aoff = ((long)(z / Hd)) * a_o + (long)(z % Hd) * a_i;
    const long boff = ((long)(z / Hd)) * b_o + (long)(z % Hd) * b_i;
    const long coff = ((long)(z / Hd)) * c_o + (long)(z % Hd) * c_i;
    const float* Ap = A + aoff + (long)m0 * lda;
    const float* Bp = B + boff + (long)n0 * ldb;
    const float* av = addv + (z % Hd) * DH_;

    const int lane = tid & 31, w = tid >> 5;
    const int g = lane >> 2, t4 = lane & 3;
    const int m_base = (w & 3) * 32;
    const int n_base = (w >> 2) * 32;

    float ra[16], rb[8];

    auto fetch = [&](int c) {
#pragma unroll
        for (int i = 0; i < 4; i++) {
            int q = tid + i * 256;
            int row = q >> 3, c4 = q & 7;
            float4 v = *(const float4*)(Ap + (long)row * lda + c * 32 + c4 * 4);
            float4 a4 = *(const float4*)(av + c * 32 + c4 * 4);
            v.x = (v.x + a4.x) * 0.125f; v.y = (v.y + a4.y) * 0.125f;
            v.z = (v.z + a4.z) * 0.125f; v.w = (v.w + a4.w) * 0.125f;
            ra[i*4+0] = v.x; ra[i*4+1] = v.y; ra[i*4+2] = v.z; ra[i*4+3] = v.w;
        }
#pragma unroll
        for (int i = 0; i < 2; i++) {
            int q = tid + i * 256;
            int nn = q >> 3, kc4 = q & 7;
            float4 v = *(const float4*)(Bp + (long)nn * ldb + c * 32 + kc4 * 4);
            rb[i*4+0] = v.x; rb[i*4+1] = v.y; rb[i*4+2] = v.z; rb[i*4+3] = v.w;
        }
    };
    auto stage = [&](int bf) {
        float* dA = sA + bf * A_BUF;
        float* dB = sB + bf * B_BUF;
#pragma unroll
        for (int i = 0; i < 4; i++) {
            int q = tid + i * 256;
            int row = q >> 3, c4 = q & 7;
            uint32_t* d = (uint32_t*)(dA + row * AS_STRIDE + c4 * 4);
            d[0] = f2tf32(ra[i*4+0]); d[1] = f2tf32(ra[i*4+1]);
            d[2] = f2tf32(ra[i*4+2]); d[3] = f2tf32(ra[i*4+3]);
        }
#pragma unroll
        for (int i = 0; i < 2; i++) {
            int q = tid + i * 256;
            int nn = q >> 3, kc4 = q & 7;
#pragma unroll
            for (int j = 0; j < 4; j++)
                *(uint32_t*)(dB + (kc4 * 4 + j) * BS_STRIDE + nn) = f2tf32(rb[i*4+j]);
        }
    };

    float acc[2][4][4] = {};
    const int nch = Kd / 32;

    fetch(0); stage(0);
    __syncthreads();

    for (int c = 0; c < nch; c++) {
        const int bf = c & 1;
        if (c + 1 < nch) fetch(c + 1);

        const float* cA = sA + bf * A_BUF;
        const float* cB = sB + bf * B_BUF;
#pragma unroll
        for (int ks = 0; ks < 4; ks++) {
            const int k = ks * 8;
            uint32_t af[2][4], bfr[4][2];
#pragma unroll
            for (int mt = 0; mt < 2; mt++) {
                const float* p = cA + (m_base + mt * 16 + g) * AS_STRIDE + k + t4;
                af[mt][0] = __float_as_uint(p[0]);
                af[mt][1] = __float_as_uint(p[8 * AS_STRIDE]);
                af[mt][2] = __float_as_uint(p[4]);
                af[mt][3] = __float_as_uint(p[8 * AS_STRIDE + 4]);
            }
#pragma unroll
            for (int nt = 0; nt < 4; nt++) {
                const float* p = cB + (k + t4) * BS_STRIDE + n_base + nt * 8 + g;
                bfr[nt][0] = __float_as_uint(p[0]);
                bfr[nt][1] = __float_as_uint(p[4 * BS_STRIDE]);
            }
#pragma unroll
            for (int mt = 0; mt < 2; mt++)
#pragma unroll
                for (int nt = 0; nt < 4; nt++)
                    mma_tf32(acc[mt][nt], af[mt], bfr[nt]);
        }
        if (c + 1 < nch) stage((c + 1) & 1);
        __syncthreads();
    }

#pragma unroll
    for (int mt = 0; mt < 2; mt++) {
#pragma unroll
        for (int half = 0; half < 2; half++) {
            const int row = m0 + m_base + mt * 16 + g + half * 8;
            float* Cr = C + coff + (long)row * ldc + n0;
#pragma unroll
            for (int nt = 0; nt < 4; nt++) {
                const int cn = n_base + nt * 8 + t4 * 2;
                float2 o;
                o.x = acc[mt][nt][half * 2 + 0];
                o.y = acc[mt][nt][half * 2 + 1];
                *(float2*)(Cr + cn) = o;
            }
        }
    }
}

// ---------------- positional embedding ----------------------------------------
__global__ void pe_kernel(float* __restrict__ pe) {
    int idx = blockIdx.x * 256 + threadIdx.x;
    int m = idx >> 9, c = idx & 511;
    double pos  = (double)(KK - m);
    int    t2   = c & 255;
    double invf = exp(-((double)(2 * t2) / 512.0) * log(10000.0));
    double a    = pos * invf;
    pe[idx] = (float)((c < 256) ? sin(a) : cos(a));
}

// ---------------- layer norm ---------------------------------------------------
__device__ __forceinline__ void ln_row(const float* __restrict__ src,
                                       float* __restrict__ dst,
                                       const float* __restrict__ g,
                                       const float* __restrict__ be, int lane) {
    float4 vals[4];
    float s = 0.f, ss = 0.f;
#pragma unroll
    for (int t = 0; t < 4; t++) {
        vals[t] = *(const float4*)(src + lane * 4 + t * 128);
        s  += vals[t].x + vals[t].y + vals[t].z + vals[t].w;
        ss += vals[t].x*vals[t].x + vals[t].y*vals[t].y
            + vals[t].z*vals[t].z + vals[t].w*vals[t].w;
    }
#pragma unroll
    for (int o = 16; o; o >>= 1) {
        s  += __shfl_xor_sync(0xffffffffu, s,  o);
        ss += __shfl_xor_sync(0xffffffffu, ss, o);
    }
    float mean = s * (1.f / 512.f);
    float var  = ss * (1.f / 512.f) - mean * mean;
    float rstd = rsqrtf(var + 1e-6f);
#pragma unroll
    for (int t = 0; t < 4; t++) {
        int e = lane * 4 + t * 128;
        float4 o4;
        o4.x = (vals[t].x - mean) * rstd * g[e+0] + be[e+0];
        o4.y = (vals[t].y - mean) * rstd * g[e+1] + be[e+1];
        o4.z = (vals[t].z - mean) * rstd * g[e+2] + be[e+2];
        o4.w = (vals[t].w - mean) * rstd * g[e+3] + be[e+3];
        *(float4*)(dst + e) = o4;
    }
}

__global__ void ln_concat_k(const float* __restrict__ mem, const float* __restrict__ x,
                            const float* __restrict__ gam, const float* __restrict__ bet,
                            float* __restrict__ out, int l) {
    int row  = blockIdx.x * 8 + (threadIdx.x >> 5);
    int lane = threadIdx.x & 31;
    int b = row >> 10, j = row & 1023;
    const float* src = (j < MEM_)
        ? (mem + ((long)(b * MEM_ + j) * LL + l) * EE)
        : (x   +  (long)(b * SS + (j - MEM_)) * EE);
    ln_row(src, out + (long)row * EE, gam + l * EE, bet + l * EE, lane);
}

__global__ void ln_plain_k(const float* __restrict__ in,
                           const float* __restrict__ gam, const float* __restrict__ bet,
                           float* __restrict__ out, int l) {
    int row  = blockIdx.x * 8 + (threadIdx.x >> 5);
    int lane = threadIdx.x & 31;
    ln_row(in + (long)row * EE, out + (long)row * EE, gam + l * EE, bet + l * EE, lane);
}

// ---------------- masked rel-shift softmax (warp per row, in-place) ------------
__global__ __launch_bounds__(256)
void softmax_k(float* __restrict__ sc, const float* __restrict__ P) {
    long row = (long)blockIdx.x * 8 + (threadIdx.x >> 5);
    int lane = threadIdx.x & 31;
    int i = (int)(row & (SS - 1));
    int jmax = MEM_ + i;
    float* srow = sc + row * KK;
    const float* prow = P + row * KK + (SS - 1 - i);
    float v[32];
    float mx = -1e30f;
#pragma unroll
    for (int t = 0; t < 32; t++) {
        int j = t * 32 + lane;
        float x = -1e30f;
        if (j <= jmax) x = srow[j] + prow[j];
        v[t] = x;
        mx = fmaxf(mx, x);
    }
#pragma unroll
    for (int o = 16; o; o >>= 1) mx = fmaxf(mx, __shfl_xor_sync(0xffffffffu, mx, o));
    float s = 0.f;
#pragma unroll
    for (int t = 0; t < 32; t++) {
        float e = (v[t] > -1e29f) ? __expf(v[t] - mx) : 0.f;
        v[t] = e; s += e;
    }
#pragma unroll
    for (int o = 16; o; o >>= 1) s += __shfl_xor_sync(0xffffffffu, s, o);
    float inv = 1.f / s;
#pragma unroll
    for (int t = 0; t < 32; t++) srow[t * 32 + lane] = v[t] * inv;
}

// ---------------- host orchestration ------------------------------------------
extern "C" void kernel_launch(void* const* d_in, const int* in_sizes, int n_in,
                              void* d_out, int out_size) {
    (void)in_sizes; (void)n_in; (void)out_size;
    const float* obs    = (const float*)d_in[0];
    const float* mems   = (const float*)d_in[1];
    const float* W_enc  = (const float*)d_in[3];
    const float* b_enc  = (const float*)d_in[4];
    const float* ln1_s  = (const float*)d_in[5];
    const float* ln1_b  = (const float*)d_in[6];
    const float* Wq     = (const float*)d_in[7];
    const float* bq     = (const float*)d_in[8];
    const float* Wk     = (const float*)d_in[9];
    const float* bk     = (const float*)d_in[10];
    const float* Wv     = (const float*)d_in[11];
    const float* bv     = (const float*)d_in[12];
    const float* Wr     = (const float*)d_in[13];
    const float* ub     = (const float*)d_in[14];
    const float* vbias  = (const float*)d_in[15];
    const float* Wo     = (const float*)d_in[16];
    const float* bo     = (const float*)d_in[17];
    const float* ln2_s  = (const float*)d_in[18];
    const float* ln2_b  = (const float*)d_in[19];
    const float* W1     = (const float*)d_in[20];
    const float* b1     = (const float*)d_in[21];
    const float* W2     = (const float*)d_in[22];
    const float* b2     = (const float*)d_in[23];
    float* out = (float*)d_out;

    float *px, *ph, *phn, *pt, *pvk, *pq, *pk, *pv_, *po, *pr, *ppe, *psc, *pP;
    cudaGetSymbolAddress((void**)&px,  g_x);
    cudaGetSymbolAddress((void**)&ph,  g_h);
    cudaGetSymbolAddress((void**)&phn, g_hn);
    cudaGetSymbolAddress((void**)&pt,  g_t);
    cudaGetSymbolAddress((void**)&pvk, g_vk);
    cudaGetSymbolAddress((void**)&pq,  g_q);
    cudaGetSymbolAddress((void**)&pk,  g_k);
    cudaGetSymbolAddress((void**)&pv_, g_v);
    cudaGetSymbolAddress((void**)&po,  g_o);
    cudaGetSymbolAddress((void**)&pr,  g_r);
    cudaGetSymbolAddress((void**)&ppe, g_pe);
    cudaGetSymbolAddress((void**)&psc, g_sc);
    cudaGetSymbolAddress((void**)&pP,  g_P);

    cudaFuncSetAttribute(mma_gemm_ca<0>, cudaFuncAttributeMaxDynamicSharedMemorySize, CA_SMEM_BYTES);
    cudaFuncSetAttribute(mma_gemm_ca<1>, cudaFuncAttributeMaxDynamicSharedMemorySize, CA_SMEM_BYTES);
    cudaFuncSetAttribute(mma_gemm_ca<2>, cudaFuncAttributeMaxDynamicSharedMemorySize, CA_SMEM_BYTES);
    cudaFuncSetAttribute(mma_gemm_ca<3>, cudaFuncAttributeMaxDynamicSharedMemorySize, CA_SMEM_BYTES);
    cudaFuncSetAttribute(mma_gemm_sc, cudaFuncAttributeMaxDynamicSharedMemorySize, SMEM_BYTES);

    const long SE = (long)SS * EE, KE = (long)KK * EE, SK = (long)SS * KK;
    const long HSK = (long)HH * SK;

    // encoder: x = obs @ W_enc + b_enc
    mma_gemm_ca<1><<<dim3(8, 32, 1), 256, CA_SMEM_BYTES>>>(
        obs, 0, 0, OBS_, W_enc, 0, 0, EE, px, 0, 0, EE,
        b_enc, nullptr, 1, OBS_);
    pe_kernel<<<(KK * EE) / 256, 256>>>(ppe);

    for (int l = 0; l < LL; l++) {
        ln_concat_k<<<(BB * KK) / 8, 256>>>(mems, px, ln1_s, ln1_b, pvk, l);

        mma_gemm_ca<1><<<dim3(8, 64, 1), 256, CA_SMEM_BYTES>>>(
            pvk, 0, 0, EE, Wk + (long)l * LW, 0, 0, EE, pk, 0, 0, EE,
            bk + l * EE, nullptr, 1, EE);
        mma_gemm_ca<1><<<dim3(8, 64, 1), 256, CA_SMEM_BYTES>>>(
            pvk, 0, 0, EE, Wv + (long)l * LW, 0, 0, EE, pv_, 0, 0, EE,
            bv + l * EE, nullptr, 1, EE);
        mma_gemm_ca<1><<<dim3(8, 4, BB), 256, CA_SMEM_BYTES>>>(
            pvk + (long)MEM_ * EE, KE, 0, EE, Wq + (long)l * LW, 0, 0, EE,
            pq, SE, 0, EE, bq + l * EE, nullptr, 1, EE);
        mma_gemm_ca<0><<<dim3(8, 8, 1), 256, CA_SMEM_BYTES>>>(
            ppe, 0, 0, EE, Wr + (long)l * LW, 0, 0, EE, pr, 0, 0, EE,
            nullptr, nullptr, 1, EE);

        // AC = ((q+u)*0.125) @ k^T
        mma_gemm_sc<<<dim3(16, 4, BB*HH), 256, SMEM_BYTES>>>(
            pq, SE, DH_, EE, pk, KE, DH_, EE, psc, HSK, SK, KK,
            ub + (long)l * EE, HH, DH_);
        // P = ((q+v)*0.125) @ r^T
        mma_gemm_sc<<<dim3(16, 4, BB*HH), 256, SMEM_BYTES>>>(
            pq, SE, DH_, EE, pr, 0, DH_, EE, pP, HSK, SK, KK,
            vbias + (long)l * EE, HH, DH_);

        softmax_k<<<(BB * HH * SS) / 8, 256>>>(psc, pP);

        // o = probs @ v
        mma_gemm_ca<0><<<dim3(1, 4, BB*HH), 256, CA_SMEM_BYTES>>>(
            psc, HSK, SK, KK, pv_, KE, DH_, EE, po, SE, DH_, EE,
            nullptr, nullptr, HH, KK);

        mma_gemm_ca<3><<<dim3(8, 32, 1), 256, CA_SMEM_BYTES>>>(
            po, 0, 0, EE, Wo + (long)l * LW, 0, 0, EE, ph, 0, 0, EE,
            bo + l * EE, px, 1, EE);
        ln_plain_k<<<(BB * SS) / 8, 256>>>(ph, ln2_s, ln2_b, phn, l);
        mma_gemm_ca<2><<<dim3(8, 32, 1), 256, CA_SMEM_BYTES>>>(
            phn, 0, 0, EE, W1 + (long)l * LW, 0, 0, EE, pt, 0, 0, EE,
            b1 + l * EE, nullptr, 1, EE);
        float* xo = (l == LL - 1) ? out : px;
        mma_gemm_ca<3><<<dim3(8, 32, 1), 256, CA_SMEM_BYTES>>>(
            pt, 0, 0, EE, W2 + (long)l * LW, 0, 0, EE, xo, 0, 0, EE,
            b2 + l * EE, ph, 1, EE);
    }
}

// round 8
// speedup vs baseline: 1.7965x; 1.0303x over previous
#include <cuda_runtime.h>
#include <cstdint>

// Shapes (fixed)
#define BB   8
#define SS   512
#define MEM_ 512
#define LL   4
#define EE   512
#define HH   8
#define DH_  64
#define OBS_ 128
#define KK   1024   // MEM + S
#define LW   (EE*EE)

// ---------------- scratch (static device globals) -----------------------------
__device__ float g_x [BB*SS*EE];
__device__ float g_h [BB*SS*EE];
__device__ float g_hn[BB*SS*EE];
__device__ float g_t [BB*SS*EE];
__device__ float g_vk[BB*KK*EE];
__device__ float g_q [BB*SS*EE];
__device__ float g_k [BB*KK*EE];
__device__ float g_v [BB*KK*EE];
__device__ float g_o [BB*SS*EE];
__device__ float g_r [KK*EE];
__device__ float g_pe[KK*EE];
__device__ float g_sc[(long)BB*HH*SS*KK];   // scores / probs (in-place)
__device__ float g_P [(long)BB*HH*SS*KK];   // rel-position term

// ---------------- helpers ------------------------------------------------------
__device__ __forceinline__ uint32_t f2tf32(float x) {
    uint32_t o;
    asm("cvt.rna.tf32.f32 %0, %1;" : "=r"(o) : "f"(x));
    return o;
}
__device__ __forceinline__ uint32_t smem_u32(const void* p) {
    uint32_t a;
    asm("{ .reg .u64 t; cvta.to.shared.u64 t, %1; cvt.u32.u64 %0, t; }"
        : "=r"(a) : "l"(p));
    return a;
}
__device__ __forceinline__ void cp_async16(uint32_t dst, const void* src) {
    asm volatile("cp.async.cg.shared.global [%0], [%1], 16;"
                 :: "r"(dst), "l"(src) : "memory");
}
__device__ __forceinline__ void cp_commit() {
    asm volatile("cp.async.commit_group;" ::: "memory");
}
__device__ __forceinline__ void cp_wait1() {
    asm volatile("cp.async.wait_group 1;" ::: "memory");
}
__device__ __forceinline__ void mma_tf32(float* d, const uint32_t* a, const uint32_t* b) {
    asm volatile(
        "mma.sync.aligned.m16n8k8.row.col.f32.tf32.tf32.f32 "
        "{%0,%1,%2,%3}, {%4,%5,%6,%7}, {%8,%9}, {%0,%1,%2,%3};"
        : "+f"(d[0]), "+f"(d[1]), "+f"(d[2]), "+f"(d[3])
        : "r"(a[0]), "r"(a[1]), "r"(a[2]), "r"(a[3]), "r"(b[0]), "r"(b[1]));
}
__device__ __forceinline__ float gelu_f(float x) {
    return 0.5f * x * (1.0f + tanhf(0.7978845608028654f * (x + 0.044715f * x * x * x)));
}

#define AS_STRIDE 36
#define BS_STRIDE 72
#define A_BUF (128 * AS_STRIDE)
#define B_BUF (32 * BS_STRIDE)

// ---------------- cp.async pipelined tf32 GEMM (BTR=false, no AADD) ------------
// C[z][m,n] = A[z][m,:] @ B[z][:,n], tile 128x64, BK=32, 2-stage cp.async.
// 2 stages -> 55.3KB smem -> 3 blocks/SM (regs-limited), occupancy ~37%.
#define PIPE 2
#define STAGE_FLOATS (A_BUF + B_BUF)
#define CA_SMEM_BYTES (PIPE * STAGE_FLOATS * 4)

template<int EPI>
__global__ __launch_bounds__(256)
void mma_gemm_ca(const float* __restrict__ A, long a_o, long a_i, int lda,
                 const float* __restrict__ B, long b_o, long b_i, int ldb,
                 float* __restrict__ C, long c_o, long c_i, int ldc,
                 const float* __restrict__ bias, const float* __restrict__ resid,
                 int Hd, int Kd) {
    extern __shared__ float smem[];
    const uint32_t sbase = smem_u32(smem);

    const int tid = threadIdx.x;
    const int z = blockIdx.z;
    const int m0 = blockIdx.y * 128;
    const int n0 = blockIdx.x * 64;

    const long aoff = ((long)(z / Hd)) * a_o + (long)(z % Hd) * a_i;
    const long boff = ((long)(z / Hd)) * b_o + (long)(z % Hd) * b_i;
    const long coff = ((long)(z / Hd)) * c_o + (long)(z % Hd) * c_i;
    const float* Ap = A + aoff + (long)m0 * lda;
    const float* Bp = B + boff + (long)n0;

    const int lane = tid & 31, w = tid >> 5;
    const int g = lane >> 2, t4 = lane & 3;
    const int m_base = (w & 3) * 32;
    const int n_base = (w >> 2) * 32;

    const int a_row = tid >> 3, a_c4 = (tid & 7) * 4;      // A: 4 iters stride 32 rows
    const int b_kr = tid >> 4, b_c4 = (tid & 15) * 4;      // B: 2 iters stride 16 rows

    auto issue_stage = [&](int c, int s) {
        uint32_t sa = sbase + (uint32_t)(s * STAGE_FLOATS) * 4u;
        uint32_t sb = sa + (uint32_t)A_BUF * 4u;
#pragma unroll
        for (int i = 0; i < 4; i++) {
            int row = a_row + i * 32;
            cp_async16(sa + (uint32_t)(row * AS_STRIDE + a_c4) * 4u,
                       Ap + (long)row * lda + c * 32 + a_c4);
        }
#pragma unroll
        for (int i = 0; i < 2; i++) {
            int kr = b_kr + i * 16;
            cp_async16(sb + (uint32_t)(kr * BS_STRIDE + b_c4) * 4u,
                       Bp + (long)(c * 32 + kr) * ldb + b_c4);
        }
    };

    const int nch = Kd / 32;
    // prologue: stage 0
    issue_stage(0, 0);
    cp_commit();

    float acc[2][4][4] = {};

    for (int c = 0; c < nch; c++) {
        // issue next stage into the buffer freed at end of iteration c-1
        if (c + 1 < nch) issue_stage(c + 1, (c + 1) & 1);
        cp_commit();             // exactly one group per iteration (may be empty)
        cp_wait1();              // all but newest group done -> stage c complete
        __syncthreads();

        const float* cA = smem + (c & 1) * STAGE_FLOATS;
        const float* cB = cA + A_BUF;
#pragma unroll
        for (int ks = 0; ks < 4; ks++) {
            const int k = ks * 8;
            uint32_t af[2][4], bfr[4][2];
#pragma unroll
            for (int mt = 0; mt < 2; mt++) {
                const float* p = cA + (m_base + mt * 16 + g) * AS_STRIDE + k + t4;
                af[mt][0] = f2tf32(p[0]);
                af[mt][1] = f2tf32(p[8 * AS_STRIDE]);
                af[mt][2] = f2tf32(p[4]);
                af[mt][3] = f2tf32(p[8 * AS_STRIDE + 4]);
            }
#pragma unroll
            for (int nt = 0; nt < 4; nt++) {
                const float* p = cB + (k + t4) * BS_STRIDE + n_base + nt * 8 + g;
                bfr[nt][0] = f2tf32(p[0]);
                bfr[nt][1] = f2tf32(p[4 * BS_STRIDE]);
            }
#pragma unroll
            for (int mt = 0; mt < 2; mt++)
#pragma unroll
                for (int nt = 0; nt < 4; nt++)
                    mma_tf32(acc[mt][nt], af[mt], bfr[nt]);
        }
        __syncthreads();         // protect this buffer before next iteration writes it
    }

    // ---- epilogue ----
#pragma unroll
    for (int mt = 0; mt < 2; mt++) {
#pragma unroll
        for (int half = 0; half < 2; half++) {
            const int row = m0 + m_base + mt * 16 + g + half * 8;
            float* Cr = C + coff + (long)row * ldc + n0;
            const float* Rr = (EPI == 3) ? (resid + coff + (long)row * ldc + n0) : nullptr;
#pragma unroll
            for (int nt = 0; nt < 4; nt++) {
                const int cn = n_base + nt * 8 + t4 * 2;
                float2 o;
                o.x = acc[mt][nt][half * 2 + 0];
                o.y = acc[mt][nt][half * 2 + 1];
                if (EPI >= 1) {
                    float2 b2 = *(const float2*)(bias + n0 + cn);
                    o.x += b2.x; o.y += b2.y;
                }
                if (EPI == 2) { o.x = gelu_f(o.x); o.y = gelu_f(o.y); }
                if (EPI == 3) {
                    float2 r2 = *(const float2*)(Rr + cn);
                    o.x += r2.x; o.y += r2.y;
                }
                *(float2*)(Cr + cn) = o;
            }
        }
    }
}

// ---------------- original register-prefetch GEMM (AC/P path: BTR+AADD) -------
#define SMEM_FLOATS (2 * (A_BUF + B_BUF))
#define SMEM_BYTES (SMEM_FLOATS * 4)

__global__ __launch_bounds__(256)
void mma_gemm_sc(const float* __restrict__ A, long a_o, long a_i, int lda,
                 const float* __restrict__ B, long b_o, long b_i, int ldb,
                 float* __restrict__ C, long c_o, long c_i, int ldc,
                 const float* __restrict__ addv, int Hd, int Kd) {
    extern __shared__ float smem[];
    float* sA = smem;
    float* sB = smem + 2 * A_BUF;

    const int tid = threadIdx.x;
    const int z = blockIdx.z;
    const int m0 = blockIdx.y * 128;
    const int n0 = blockIdx.x * 64;

    const long aoff = ((long)(z / Hd)) * a_o + (long)(z % Hd) * a_i;
    const long boff = ((long)(z / Hd)) * b_o + (long)(z % Hd) * b_i;
    const long coff = ((long)(z / Hd)) * c_o + (long)(z % Hd) * c_i;
    const float* Ap = A + aoff + (long)m0 * lda;
    const float* Bp = B + boff + (long)n0 * ldb;
    const float* av = addv + (z % Hd) * DH_;

    const int lane = tid & 31, w = tid >> 5;
    const int g = lane >> 2, t4 = lane & 3;
    const int m_base = (w & 3) * 32;
    const int n_base = (w >> 2) * 32;

    float ra[16], rb[8];

    auto fetch = [&](int c) {
#pragma unroll
        for (int i = 0; i < 4; i++) {
            int q = tid + i * 256;
            int row = q >> 3, c4 = q & 7;
            float4 v = *(const float4*)(Ap + (long)row * lda + c * 32 + c4 * 4);
            float4 a4 = *(const float4*)(av + c * 32 + c4 * 4);
            v.x = (v.x + a4.x) * 0.125f; v.y = (v.y + a4.y) * 0.125f;
            v.z = (v.z + a4.z) * 0.125f; v.w = (v.w + a4.w) * 0.125f;
            ra[i*4+0] = v.x; ra[i*4+1] = v.y; ra[i*4+2] = v.z; ra[i*4+3] = v.w;
        }
#pragma unroll
        for (int i = 0; i < 2; i++) {
            int q = tid + i * 256;
            int nn = q >> 3, kc4 = q & 7;
            float4 v = *(const float4*)(Bp + (long)nn * ldb + c * 32 + kc4 * 4);
            rb[i*4+0] = v.x; rb[i*4+1] = v.y; rb[i*4+2] = v.z; rb[i*4+3] = v.w;
        }
    };
    auto stage = [&](int bf) {
        float* dA = sA + bf * A_BUF;
        float* dB = sB + bf * B_BUF;
#pragma unroll
        for (int i = 0; i < 4; i++) {
            int q = tid + i * 256;
            int row = q >> 3, c4 = q & 7;
            uint32_t* d = (uint32_t*)(dA + row * AS_STRIDE + c4 * 4);
            d[0] = f2tf32(ra[i*4+0]); d[1] = f2tf32(ra[i*4+1]);
            d[2] = f2tf32(ra[i*4+2]); d[3] = f2tf32(ra[i*4+3]);
        }
#pragma unroll
        for (int i = 0; i < 2; i++) {
            int q = tid + i * 256;
            int nn = q >> 3, kc4 = q & 7;
#pragma unroll
            for (int j = 0; j < 4; j++)
                *(uint32_t*)(dB + (kc4 * 4 + j) * BS_STRIDE + nn) = f2tf32(rb[i*4+j]);
        }
    };

    float acc[2][4][4] = {};
    const int nch = Kd / 32;

    fetch(0); stage(0);
    __syncthreads();

    for (int c = 0; c < nch; c++) {
        const int bf = c & 1;
        if (c + 1 < nch) fetch(c + 1);

        const float* cA = sA + bf * A_BUF;
        const float* cB = sB + bf * B_BUF;
#pragma unroll
        for (int ks = 0; ks < 4; ks++) {
            const int k = ks * 8;
            uint32_t af[2][4], bfr[4][2];
#pragma unroll
            for (int mt = 0; mt < 2; mt++) {
                const float* p = cA + (m_base + mt * 16 + g) * AS_STRIDE + k + t4;
                af[mt][0] = __float_as_uint(p[0]);
                af[mt][1] = __float_as_uint(p[8 * AS_STRIDE]);
                af[mt][2] = __float_as_uint(p[4]);
                af[mt][3] = __float_as_uint(p[8 * AS_STRIDE + 4]);
            }
#pragma unroll
            for (int nt = 0; nt < 4; nt++) {
                const float* p = cB + (k + t4) * BS_STRIDE + n_base + nt * 8 + g;
                bfr[nt][0] = __float_as_uint(p[0]);
                bfr[nt][1] = __float_as_uint(p[4 * BS_STRIDE]);
            }
#pragma unroll
            for (int mt = 0; mt < 2; mt++)
#pragma unroll
                for (int nt = 0; nt < 4; nt++)
                    mma_tf32(acc[mt][nt], af[mt], bfr[nt]);
        }
        if (c + 1 < nch) stage((c + 1) & 1);
        __syncthreads();
    }

#pragma unroll
    for (int mt = 0; mt < 2; mt++) {
#pragma unroll
        for (int half = 0; half < 2; half++) {
            const int row = m0 + m_base + mt * 16 + g + half * 8;
            float* Cr = C + coff + (long)row * ldc + n0;
#pragma unroll
            for (int nt = 0; nt < 4; nt++) {
                const int cn = n_base + nt * 8 + t4 * 2;
                float2 o;
                o.x = acc[mt][nt][half * 2 + 0];
                o.y = acc[mt][nt][half * 2 + 1];
                *(float2*)(Cr + cn) = o;
            }
        }
    }
}

// ---------------- positional embedding ----------------------------------------
__global__ void pe_kernel(float* __restrict__ pe) {
    int idx = blockIdx.x * 256 + threadIdx.x;
    int m = idx >> 9, c = idx & 511;
    double pos  = (double)(KK - m);
    int    t2   = c & 255;
    double invf = exp(-((double)(2 * t2) / 512.0) * log(10000.0));
    double a    = pos * invf;
    pe[idx] = (float)((c < 256) ? sin(a) : cos(a));
}

// ---------------- layer norm ---------------------------------------------------
__device__ __forceinline__ void ln_row(const float* __restrict__ src,
                                       float* __restrict__ dst,
                                       const float* __restrict__ g,
                                       const float* __restrict__ be, int lane) {
    float4 vals[4];
    float s = 0.f, ss = 0.f;
#pragma unroll
    for (int t = 0; t < 4; t++) {
        vals[t] = *(const float4*)(src + lane * 4 + t * 128);
        s  += vals[t].x + vals[t].y + vals[t].z + vals[t].w;
        ss += vals[t].x*vals[t].x + vals[t].y*vals[t].y
            + vals[t].z*vals[t].z + vals[t].w*vals[t].w;
    }
#pragma unroll
    for (int o = 16; o; o >>= 1) {
        s  += __shfl_xor_sync(0xffffffffu, s,  o);
        ss += __shfl_xor_sync(0xffffffffu, ss, o);
    }
    float mean = s * (1.f / 512.f);
    float var  = ss * (1.f / 512.f) - mean * mean;
    float rstd = rsqrtf(var + 1e-6f);
#pragma unroll
    for (int t = 0; t < 4; t++) {
        int e = lane * 4 + t * 128;
        float4 o4;
        o4.x = (vals[t].x - mean) * rstd * g[e+0] + be[e+0];
        o4.y = (vals[t].y - mean) * rstd * g[e+1] + be[e+1];
        o4.z = (vals[t].z - mean) * rstd * g[e+2] + be[e+2];
        o4.w = (vals[t].w - mean) * rstd * g[e+3] + be[e+3];
        *(float4*)(dst + e) = o4;
    }
}

__global__ void ln_concat_k(const float* __restrict__ mem, const float* __restrict__ x,
                            const float* __restrict__ gam, const float* __restrict__ bet,
                            float* __restrict__ out, int l) {
    int row  = blockIdx.x * 8 + (threadIdx.x >> 5);
    int lane = threadIdx.x & 31;
    int b = row >> 10, j = row & 1023;
    const float* src = (j < MEM_)
        ? (mem + ((long)(b * MEM_ + j) * LL + l) * EE)
        : (x   +  (long)(b * SS + (j - MEM_)) * EE);
    ln_row(src, out + (long)row * EE, gam + l * EE, bet + l * EE, lane);
}

__global__ void ln_plain_k(const float* __restrict__ in,
                           const float* __restrict__ gam, const float* __restrict__ bet,
                           float* __restrict__ out, int l) {
    int row  = blockIdx.x * 8 + (threadIdx.x >> 5);
    int lane = threadIdx.x & 31;
    ln_row(in + (long)row * EE, out + (long)row * EE, gam + l * EE, bet + l * EE, lane);
}

// ---------------- masked rel-shift softmax (warp per row, in-place) ------------
__global__ __launch_bounds__(256)
void softmax_k(float* __restrict__ sc, const float* __restrict__ P) {
    long row = (long)blockIdx.x * 8 + (threadIdx.x >> 5);
    int lane = threadIdx.x & 31;
    int i = (int)(row & (SS - 1));
    int jmax = MEM_ + i;
    float* srow = sc + row * KK;
    const float* prow = P + row * KK + (SS - 1 - i);
    float v[32];
    float mx = -1e30f;
#pragma unroll
    for (int t = 0; t < 32; t++) {
        int j = t * 32 + lane;
        float x = -1e30f;
        if (j <= jmax) x = srow[j] + prow[j];
        v[t] = x;
        mx = fmaxf(mx, x);
    }
#pragma unroll
    for (int o = 16; o; o >>= 1) mx = fmaxf(mx, __shfl_xor_sync(0xffffffffu, mx, o));
    float s = 0.f;
#pragma unroll
    for (int t = 0; t < 32; t++) {
        float e = (v[t] > -1e29f) ? __expf(v[t] - mx) : 0.f;
        v[t] = e; s += e;
    }
#pragma unroll
    for (int o = 16; o; o >>= 1) s += __shfl_xor_sync(0xffffffffu, s, o);
    float inv = 1.f / s;
#pragma unroll
    for (int t = 0; t < 32; t++) srow[t * 32 + lane] = v[t] * inv;
}

// ---------------- host orchestration ------------------------------------------
extern "C" void kernel_launch(void* const* d_in, const int* in_sizes, int n_in,
                              void* d_out, int out_size) {
    (void)in_sizes; (void)n_in; (void)out_size;
    const float* obs    = (const float*)d_in[0];
    const float* mems   = (const float*)d_in[1];
    const float* W_enc  = (const float*)d_in[3];
    const float* b_enc  = (const float*)d_in[4];
    const float* ln1_s  = (const float*)d_in[5];
    const float* ln1_b  = (const float*)d_in[6];
    const float* Wq     = (const float*)d_in[7];
    const float* bq     = (const float*)d_in[8];
    const float* Wk     = (const float*)d_in[9];
    const float* bk     = (const float*)d_in[10];
    const float* Wv     = (const float*)d_in[11];
    const float* bv     = (const float*)d_in[12];
    const float* Wr     = (const float*)d_in[13];
    const float* ub     = (const float*)d_in[14];
    const float* vbias  = (const float*)d_in[15];
    const float* Wo     = (const float*)d_in[16];
    const float* bo     = (const float*)d_in[17];
    const float* ln2_s  = (const float*)d_in[18];
    const float* ln2_b  = (const float*)d_in[19];
    const float* W1     = (const float*)d_in[20];
    const float* b1     = (const float*)d_in[21];
    const float* W2     = (const float*)d_in[22];
    const float* b2     = (const float*)d_in[23];
    float* out = (float*)d_out;

    float *px, *ph, *phn, *pt, *pvk, *pq, *pk, *pv_, *po, *pr, *ppe, *psc, *pP;
    cudaGetSymbolAddress((void**)&px,  g_x);
    cudaGetSymbolAddress((void**)&ph,  g_h);
    cudaGetSymbolAddress((void**)&phn, g_hn);
    cudaGetSymbolAddress((void**)&pt,  g_t);
    cudaGetSymbolAddress((void**)&pvk, g_vk);
    cudaGetSymbolAddress((void**)&pq,  g_q);
    cudaGetSymbolAddress((void**)&pk,  g_k);
    cudaGetSymbolAddress((void**)&pv_, g_v);
    cudaGetSymbolAddress((void**)&po,  g_o);
    cudaGetSymbolAddress((void**)&pr,  g_r);
    cudaGetSymbolAddress((void**)&ppe, g_pe);
    cudaGetSymbolAddress((void**)&psc, g_sc);
    cudaGetSymbolAddress((void**)&pP,  g_P);

    cudaFuncSetAttribute(mma_gemm_ca<0>, cudaFuncAttributeMaxDynamicSharedMemorySize, CA_SMEM_BYTES);
    cudaFuncSetAttribute(mma_gemm_ca<1>, cudaFuncAttributeMaxDynamicSharedMemorySize, CA_SMEM_BYTES);
    cudaFuncSetAttribute(mma_gemm_ca<2>, cudaFuncAttributeMaxDynamicSharedMemorySize, CA_SMEM_BYTES);
    cudaFuncSetAttribute(mma_gemm_ca<3>, cudaFuncAttributeMaxDynamicSharedMemorySize, CA_SMEM_BYTES);
    cudaFuncSetAttribute(mma_gemm_sc, cudaFuncAttributeMaxDynamicSharedMemorySize, SMEM_BYTES);

    const long SE = (long)SS * EE, KE = (long)KK * EE, SK = (long)SS * KK;
    const long HSK = (long)HH * SK;

    // encoder: x = obs @ W_enc + b_enc
    mma_gemm_ca<1><<<dim3(8, 32, 1), 256, CA_SMEM_BYTES>>>(
        obs, 0, 0, OBS_, W_enc, 0, 0, EE, px, 0, 0, EE,
        b_enc, nullptr, 1, OBS_);
    pe_kernel<<<(KK * EE) / 256, 256>>>(ppe);

    for (int l = 0; l < LL; l++) {
        ln_concat_k<<<(BB * KK) / 8, 256>>>(mems, px, ln1_s, ln1_b, pvk, l);

        mma_gemm_ca<1><<<dim3(8, 64, 1), 256, CA_SMEM_BYTES>>>(
            pvk, 0, 0, EE, Wk + (long)l * LW, 0, 0, EE, pk, 0, 0, EE,
            bk + l * EE, nullptr, 1, EE);
        mma_gemm_ca<1><<<dim3(8, 64, 1), 256, CA_SMEM_BYTES>>>(
            pvk, 0, 0, EE, Wv + (long)l * LW, 0, 0, EE, pv_, 0, 0, EE,
            bv + l * EE, nullptr, 1, EE);
        mma_gemm_ca<1><<<dim3(8, 4, BB), 256, CA_SMEM_BYTES>>>(
            pvk + (long)MEM_ * EE, KE, 0, EE, Wq + (long)l * LW, 0, 0, EE,
            pq, SE, 0, EE, bq + l * EE, nullptr, 1, EE);
        mma_gemm_ca<0><<<dim3(8, 8, 1), 256, CA_SMEM_BYTES>>>(
            ppe, 0, 0, EE, Wr + (long)l * LW, 0, 0, EE, pr, 0, 0, EE,
            nullptr, nullptr, 1, EE);

        // AC = ((q+u)*0.125) @ k^T
        mma_gemm_sc<<<dim3(16, 4, BB*HH), 256, SMEM_BYTES>>>(
            pq, SE, DH_, EE, pk, KE, DH_, EE, psc, HSK, SK, KK,
            ub + (long)l * EE, HH, DH_);
        // P = ((q+v)*0.125) @ r^T
        mma_gemm_sc<<<dim3(16, 4, BB*HH), 256, SMEM_BYTES>>>(
            pq, SE, DH_, EE, pr, 0, DH_, EE, pP, HSK, SK, KK,
            vbias + (long)l * EE, HH, DH_);

        softmax_k<<<(BB * HH * SS) / 8, 256>>>(psc, pP);

        // o = probs @ v
        mma_gemm_ca<0><<<dim3(1, 4, BB*HH), 256, CA_SMEM_BYTES>>>(
            psc, HSK, SK, KK, pv_, KE, DH_, EE, po, SE, DH_, EE,
            nullptr, nullptr, HH, KK);

        mma_gemm_ca<3><<<dim3(8, 32, 1), 256, CA_SMEM_BYTES>>>(
            po, 0, 0, EE, Wo + (long)l * LW, 0, 0, EE, ph, 0, 0, EE,
            bo + l * EE, px, 1, EE);
        ln_plain_k<<<(BB * SS) / 8, 256>>>(ph, ln2_s, ln2_b, phn, l);
        mma_gemm_ca<2><<<dim3(8, 32, 1), 256, CA_SMEM_BYTES>>>(
            phn, 0, 0, EE, W1 + (long)l * LW, 0, 0, EE, pt, 0, 0, EE,
            b1 + l * EE, nullptr, 1, EE);
        float* xo = (l == LL - 1) ? out : px;
        mma_gemm_ca<3><<<dim3(8, 32, 1), 256, CA_SMEM_BYTES>>>(
            pt, 0, 0, EE, W2 + (long)l * LW, 0, 0, EE, xo, 0, 0, EE,
            b2 + l * EE, ph, 1, EE);
    }
}

// round 9
// speedup vs baseline: 1.8572x; 1.0338x over previous
#include <cuda_runtime.h>
#include <cstdint>

// Shapes (fixed)
#define BB   8
#define SS   512
#define MEM_ 512
#define LL   4
#define EE   512
#define HH   8
#define DH_  64
#define OBS_ 128
#define KK   1024   // MEM + S
#define LW   (EE*EE)

// ---------------- scratch (static device globals) -----------------------------
__device__ float g_x [BB*SS*EE];
__device__ float g_h [BB*SS*EE];
__device__ float g_hn[BB*SS*EE];
__device__ float g_t [BB*SS*EE];
__device__ float g_vk[BB*KK*EE];
__device__ float g_q [BB*SS*EE];
__device__ float g_k [BB*KK*EE];
__device__ float g_v [BB*KK*EE];
__device__ float g_o [BB*SS*EE];
__device__ float g_r [KK*EE];
__device__ float g_pe[KK*EE];
__device__ float g_sc[(long)BB*HH*SS*KK];   // scores / probs (in-place)
__device__ float g_P [(long)BB*HH*SS*KK];   // rel-position term

// ---------------- helpers ------------------------------------------------------
__device__ __forceinline__ uint32_t f2tf32(float x) {
    uint32_t o;
    asm("cvt.rna.tf32.f32 %0, %1;" : "=r"(o) : "f"(x));
    return o;
}
__device__ __forceinline__ uint32_t smem_u32(const void* p) {
    uint32_t a;
    asm("{ .reg .u64 t; cvta.to.shared.u64 t, %1; cvt.u32.u64 %0, t; }"
        : "=r"(a) : "l"(p));
    return a;
}
__device__ __forceinline__ void cp_async16(uint32_t dst, const void* src) {
    asm volatile("cp.async.cg.shared.global [%0], [%1], 16;"
                 :: "r"(dst), "l"(src) : "memory");
}
__device__ __forceinline__ void cp_commit() {
    asm volatile("cp.async.commit_group;" ::: "memory");
}
__device__ __forceinline__ void cp_wait1() {
    asm volatile("cp.async.wait_group 1;" ::: "memory");
}
__device__ __forceinline__ void mma_tf32(float* d, const uint32_t* a, const uint32_t* b) {
    asm volatile(
        "mma.sync.aligned.m16n8k8.row.col.f32.tf32.tf32.f32 "
        "{%0,%1,%2,%3}, {%4,%5,%6,%7}, {%8,%9}, {%0,%1,%2,%3};"
        : "+f"(d[0]), "+f"(d[1]), "+f"(d[2]), "+f"(d[3])
        : "r"(a[0]), "r"(a[1]), "r"(a[2]), "r"(a[3]), "r"(b[0]), "r"(b[1]));
}
__device__ __forceinline__ float gelu_f(float x) {
    return 0.5f * x * (1.0f + tanhf(0.7978845608028654f * (x + 0.044715f * x * x * x)));
}

#define AS_STRIDE 36
#define BS_STRIDE 72
#define A_BUF (128 * AS_STRIDE)
#define B_BUF (32 * BS_STRIDE)

// ---------------- 128x128 tile cp.async tf32 GEMM (N multiple of 128) ----------
// warps 4(M) x 2(N): warp tile 32x64. 2-stage pipeline.
#define BS2_ST 136
#define B2_BUF (32 * BS2_ST)                 // 4352 floats
#define STAGE2_FLOATS (A_BUF + B2_BUF)       // 8960 floats
#define CB_SMEM_BYTES (2 * STAGE2_FLOATS * 4)

template<int EPI>
__global__ __launch_bounds__(256)
void mma_gemm_cb(const float* __restrict__ A, long a_o, long a_i, int lda,
                 const float* __restrict__ B, long b_o, long b_i, int ldb,
                 float* __restrict__ C, long c_o, long c_i, int ldc,
                 const float* __restrict__ bias, const float* __restrict__ resid,
                 int Hd, int Kd) {
    extern __shared__ float smem[];
    const uint32_t sbase = smem_u32(smem);

    const int tid = threadIdx.x;
    const int z = blockIdx.z;
    const int m0 = blockIdx.y * 128;
    const int n0 = blockIdx.x * 128;

    const long aoff = ((long)(z / Hd)) * a_o + (long)(z % Hd) * a_i;
    const long boff = ((long)(z / Hd)) * b_o + (long)(z % Hd) * b_i;
    const long coff = ((long)(z / Hd)) * c_o + (long)(z % Hd) * c_i;
    const float* Ap = A + aoff + (long)m0 * lda;
    const float* Bp = B + boff + (long)n0;

    const int lane = tid & 31, w = tid >> 5;
    const int g = lane >> 2, t4 = lane & 3;
    const int wm = (w & 3) * 32;     // warp M offset
    const int wn = (w >> 2) * 64;    // warp N offset

    const int a_row = tid >> 3, a_c4 = (tid & 7) * 4;
    const int b_row = tid >> 5, b_c4 = (tid & 31) * 4;

    auto issue_stage = [&](int c, int s) {
        uint32_t sa = sbase + (uint32_t)(s * STAGE2_FLOATS) * 4u;
        uint32_t sb = sa + (uint32_t)A_BUF * 4u;
#pragma unroll
        for (int i = 0; i < 4; i++) {
            int row = a_row + i * 32;
            cp_async16(sa + (uint32_t)(row * AS_STRIDE + a_c4) * 4u,
                       Ap + (long)row * lda + c * 32 + a_c4);
        }
#pragma unroll
        for (int i = 0; i < 4; i++) {
            int kr = b_row + i * 8;
            cp_async16(sb + (uint32_t)(kr * BS2_ST + b_c4) * 4u,
                       Bp + (long)(c * 32 + kr) * ldb + b_c4);
        }
    };

    const int nch = Kd / 32;
    issue_stage(0, 0);
    cp_commit();

    float acc[2][8][4] = {};

    for (int c = 0; c < nch; c++) {
        if (c + 1 < nch) issue_stage(c + 1, (c + 1) & 1);
        cp_commit();
        cp_wait1();
        __syncthreads();

        const float* cA = smem + (c & 1) * STAGE2_FLOATS;
        const float* cB = cA + A_BUF;
#pragma unroll
        for (int ks = 0; ks < 4; ks++) {
            const int k = ks * 8;
            uint32_t af[2][4], bfr[8][2];
#pragma unroll
            for (int mt = 0; mt < 2; mt++) {
                const float* p = cA + (wm + mt * 16 + g) * AS_STRIDE + k + t4;
                af[mt][0] = f2tf32(p[0]);
                af[mt][1] = f2tf32(p[8 * AS_STRIDE]);
                af[mt][2] = f2tf32(p[4]);
                af[mt][3] = f2tf32(p[8 * AS_STRIDE + 4]);
            }
#pragma unroll
            for (int nt = 0; nt < 8; nt++) {
                const float* p = cB + (k + t4) * BS2_ST + wn + nt * 8 + g;
                bfr[nt][0] = f2tf32(p[0]);
                bfr[nt][1] = f2tf32(p[4 * BS2_ST]);
            }
#pragma unroll
            for (int mt = 0; mt < 2; mt++)
#pragma unroll
                for (int nt = 0; nt < 8; nt++)
                    mma_tf32(acc[mt][nt], af[mt], bfr[nt]);
        }
        __syncthreads();
    }

    // ---- epilogue ----
#pragma unroll
    for (int mt = 0; mt < 2; mt++) {
#pragma unroll
        for (int half = 0; half < 2; half++) {
            const int row = m0 + wm + mt * 16 + g + half * 8;
            float* Cr = C + coff + (long)row * ldc + n0;
            const float* Rr = (EPI == 3) ? (resid + coff + (long)row * ldc + n0) : nullptr;
#pragma unroll
            for (int nt = 0; nt < 8; nt++) {
                const int cn = wn + nt * 8 + t4 * 2;
                float2 o;
                o.x = acc[mt][nt][half * 2 + 0];
                o.y = acc[mt][nt][half * 2 + 1];
                if (EPI >= 1) {
                    float2 b2 = *(const float2*)(bias + n0 + cn);
                    o.x += b2.x; o.y += b2.y;
                }
                if (EPI == 2) { o.x = gelu_f(o.x); o.y = gelu_f(o.y); }
                if (EPI == 3) {
                    float2 r2 = *(const float2*)(Rr + cn);
                    o.x += r2.x; o.y += r2.y;
                }
                *(float2*)(Cr + cn) = o;
            }
        }
    }
}

// ---------------- 128x64 cp.async GEMM (probs@V: N=64) -------------------------
#define PIPE 2
#define STAGE_FLOATS (A_BUF + B_BUF)
#define CA_SMEM_BYTES (PIPE * STAGE_FLOATS * 4)

template<int EPI>
__global__ __launch_bounds__(256)
void mma_gemm_ca(const float* __restrict__ A, long a_o, long a_i, int lda,
                 const float* __restrict__ B, long b_o, long b_i, int ldb,
                 float* __restrict__ C, long c_o, long c_i, int ldc,
                 const float* __restrict__ bias, const float* __restrict__ resid,
                 int Hd, int Kd) {
    extern __shared__ float smem[];
    const uint32_t sbase = smem_u32(smem);

    const int tid = threadIdx.x;
    const int z = blockIdx.z;
    const int m0 = blockIdx.y * 128;
    const int n0 = blockIdx.x * 64;

    const long aoff = ((long)(z / Hd)) * a_o + (long)(z % Hd) * a_i;
    const long boff = ((long)(z / Hd)) * b_o + (long)(z % Hd) * b_i;
    const long coff = ((long)(z / Hd)) * c_o + (long)(z % Hd) * c_i;
    const float* Ap = A + aoff + (long)m0 * lda;
    const float* Bp = B + boff + (long)n0;

    const int lane = tid & 31, w = tid >> 5;
    const int g = lane >> 2, t4 = lane & 3;
    const int m_base = (w & 3) * 32;
    const int n_base = (w >> 2) * 32;

    const int a_row = tid >> 3, a_c4 = (tid & 7) * 4;
    const int b_kr = tid >> 4, b_c4 = (tid & 15) * 4;

    auto issue_stage = [&](int c, int s) {
        uint32_t sa = sbase + (uint32_t)(s * STAGE_FLOATS) * 4u;
        uint32_t sb = sa + (uint32_t)A_BUF * 4u;
#pragma unroll
        for (int i = 0; i < 4; i++) {
            int row = a_row + i * 32;
            cp_async16(sa + (uint32_t)(row * AS_STRIDE + a_c4) * 4u,
                       Ap + (long)row * lda + c * 32 + a_c4);
        }
#pragma unroll
        for (int i = 0; i < 2; i++) {
            int kr = b_kr + i * 16;
            cp_async16(sb + (uint32_t)(kr * BS_STRIDE + b_c4) * 4u,
                       Bp + (long)(c * 32 + kr) * ldb + b_c4);
        }
    };

    const int nch = Kd / 32;
    issue_stage(0, 0);
    cp_commit();

    float acc[2][4][4] = {};

    for (int c = 0; c < nch; c++) {
        if (c + 1 < nch) issue_stage(c + 1, (c + 1) & 1);
        cp_commit();
        cp_wait1();
        __syncthreads();

        const float* cA = smem + (c & 1) * STAGE_FLOATS;
        const float* cB = cA + A_BUF;
#pragma unroll
        for (int ks = 0; ks < 4; ks++) {
            const int k = ks * 8;
            uint32_t af[2][4], bfr[4][2];
#pragma unroll
            for (int mt = 0; mt < 2; mt++) {
                const float* p = cA + (m_base + mt * 16 + g) * AS_STRIDE + k + t4;
                af[mt][0] = f2tf32(p[0]);
                af[mt][1] = f2tf32(p[8 * AS_STRIDE]);
                af[mt][2] = f2tf32(p[4]);
                af[mt][3] = f2tf32(p[8 * AS_STRIDE + 4]);
            }
#pragma unroll
            for (int nt = 0; nt < 4; nt++) {
                const float* p = cB + (k + t4) * BS_STRIDE + n_base + nt * 8 + g;
                bfr[nt][0] = f2tf32(p[0]);
                bfr[nt][1] = f2tf32(p[4 * BS_STRIDE]);
            }
#pragma unroll
            for (int mt = 0; mt < 2; mt++)
#pragma unroll
                for (int nt = 0; nt < 4; nt++)
                    mma_tf32(acc[mt][nt], af[mt], bfr[nt]);
        }
        __syncthreads();
    }

#pragma unroll
    for (int mt = 0; mt < 2; mt++) {
#pragma unroll
        for (int half = 0; half < 2; half++) {
            const int row = m0 + m_base + mt * 16 + g + half * 8;
            float* Cr = C + coff + (long)row * ldc + n0;
            const float* Rr = (EPI == 3) ? (resid + coff + (long)row * ldc + n0) : nullptr;
#pragma unroll
            for (int nt = 0; nt < 4; nt++) {
                const int cn = n_base + nt * 8 + t4 * 2;
                float2 o;
                o.x = acc[mt][nt][half * 2 + 0];
                o.y = acc[mt][nt][half * 2 + 1];
                if (EPI >= 1) {
                    float2 b2 = *(const float2*)(bias + n0 + cn);
                    o.x += b2.x; o.y += b2.y;
                }
                if (EPI == 2) { o.x = gelu_f(o.x); o.y = gelu_f(o.y); }
                if (EPI == 3) {
                    float2 r2 = *(const float2*)(Rr + cn);
                    o.x += r2.x; o.y += r2.y;
                }
                *(float2*)(Cr + cn) = o;
            }
        }
    }
}

// ---------------- register-prefetch GEMM (AC/P path: BTR+AADD) -----------------
#define SMEM_FLOATS (2 * (A_BUF + B_BUF))
#define SMEM_BYTES (SMEM_FLOATS * 4)

__global__ __launch_bounds__(256)
void mma_gemm_sc(const float* __restrict__ A, long a_o, long a_i, int lda,
                 const float* __restrict__ B, long b_o, long b_i, int ldb,
                 float* __restrict__ C, long c_o, long c_i, int ldc,
                 const float* __restrict__ addv, int Hd, int Kd) {
    extern __shared__ float smem[];
    float* sA = smem;
    float* sB = smem + 2 * A_BUF;

    const int tid = threadIdx.x;
    const int z = blockIdx.z;
    const int m0 = blockIdx.y * 128;
    const int n0 = blockIdx.x * 64;

    const long aoff = ((long)(z / Hd)) * a_o + (long)(z % Hd) * a_i;
    const long boff = ((long)(z / Hd)) * b_o + (long)(z % Hd) * b_i;
    const long coff = ((long)(z / Hd)) * c_o + (long)(z % Hd) * c_i;
    const float* Ap = A + aoff + (long)m0 * lda;
    const float* Bp = B + boff + (long)n0 * ldb;
    const float* av = addv + (z % Hd) * DH_;

    const int lane = tid & 31, w = tid >> 5;
    const int g = lane >> 2, t4 = lane & 3;
    const int m_base = (w & 3) * 32;
    const int n_base = (w >> 2) * 32;

    float ra[16], rb[8];

    auto fetch = [&](int c) {
#pragma unroll
        for (int i = 0; i < 4; i++) {
            int q = tid + i * 256;
            int row = q >> 3, c4 = q & 7;
            float4 v = *(const float4*)(Ap + (long)row * lda + c * 32 + c4 * 4);
            float4 a4 = *(const float4*)(av + c * 32 + c4 * 4);
            v.x = (v.x + a4.x) * 0.125f; v.y = (v.y + a4.y) * 0.125f;
            v.z = (v.z + a4.z) * 0.125f; v.w = (v.w + a4.w) * 0.125f;
            ra[i*4+0] = v.x; ra[i*4+1] = v.y; ra[i*4+2] = v.z; ra[i*4+3] = v.w;
        }
#pragma unroll
        for (int i = 0; i < 2; i++) {
            int q = tid + i * 256;
            int nn = q >> 3, kc4 = q & 7;
            float4 v = *(const float4*)(Bp + (long)nn * ldb + c * 32 + kc4 * 4);
            rb[i*4+0] = v.x; rb[i*4+1] = v.y; rb[i*4+2] = v.z; rb[i*4+3] = v.w;
        }
    };
    auto stage = [&](int bf) {
        float* dA = sA + bf * A_BUF;
        float* dB = sB + bf * B_BUF;
#pragma unroll
        for (int i = 0; i < 4; i++) {
            int q = tid + i * 256;
            int row = q >> 3, c4 = q & 7;
            uint32_t* d = (uint32_t*)(dA + row * AS_STRIDE + c4 * 4);
            d[0] = f2tf32(ra[i*4+0]); d[1] = f2tf32(ra[i*4+1]);
            d[2] = f2tf32(ra[i*4+2]); d[3] = f2tf32(ra[i*4+3]);
        }
#pragma unroll
        for (int i = 0; i < 2; i++) {
            int q = tid + i * 256;
            int nn = q >> 3, kc4 = q & 7;
#pragma unroll
            for (int j = 0; j < 4; j++)
                *(uint32_t*)(dB + (kc4 * 4 + j) * BS_STRIDE + nn) = f2tf32(rb[i*4+j]);
        }
    };

    float acc[2][4][4] = {};
    const int nch = Kd / 32;

    fetch(0); stage(0);
    __syncthreads();

    for (int c = 0; c < nch; c++) {
        const int bf = c & 1;
        if (c + 1 < nch) fetch(c + 1);

        const float* cA = sA + bf * A_BUF;
        const float* cB = sB + bf * B_BUF;
#pragma unroll
        for (int ks = 0; ks < 4; ks++) {
            const int k = ks * 8;
            uint32_t af[2][4], bfr[4][2];
#pragma unroll
            for (int mt = 0; mt < 2; mt++) {
                const float* p = cA + (m_base + mt * 16 + g) * AS_STRIDE + k + t4;
                af[mt][0] = __float_as_uint(p[0]);
                af[mt][1] = __float_as_uint(p[8 * AS_STRIDE]);
                af[mt][2] = __float_as_uint(p[4]);
                af[mt][3] = __float_as_uint(p[8 * AS_STRIDE + 4]);
            }
#pragma unroll
            for (int nt = 0; nt < 4; nt++) {
                const float* p = cB + (k + t4) * BS_STRIDE + n_base + nt * 8 + g;
                bfr[nt][0] = __float_as_uint(p[0]);
                bfr[nt][1] = __float_as_uint(p[4 * BS_STRIDE]);
            }
#pragma unroll
            for (int mt = 0; mt < 2; mt++)
#pragma unroll
                for (int nt = 0; nt < 4; nt++)
                    mma_tf32(acc[mt][nt], af[mt], bfr[nt]);
        }
        if (c + 1 < nch) stage((c + 1) & 1);
        __syncthreads();
    }

#pragma unroll
    for (int mt = 0; mt < 2; mt++) {
#pragma unroll
        for (int half = 0; half < 2; half++) {
            const int row = m0 + m_base + mt * 16 + g + half * 8;
            float* Cr = C + coff + (long)row * ldc + n0;
#pragma unroll
            for (int nt = 0; nt < 4; nt++) {
                const int cn = n_base + nt * 8 + t4 * 2;
                float2 o;
                o.x = acc[mt][nt][half * 2 + 0];
                o.y = acc[mt][nt][half * 2 + 1];
                *(float2*)(Cr + cn) = o;
            }
        }
    }
}

// ---------------- positional embedding ----------------------------------------
__global__ void pe_kernel(float* __restrict__ pe) {
    int idx = blockIdx.x * 256 + threadIdx.x;
    int m = idx >> 9, c = idx & 511;
    double pos  = (double)(KK - m);
    int    t2   = c & 255;
    double invf = exp(-((double)(2 * t2) / 512.0) * log(10000.0));
    double a    = pos * invf;
    pe[idx] = (float)((c < 256) ? sin(a) : cos(a));
}

// ---------------- layer norm ---------------------------------------------------
__device__ __forceinline__ void ln_row(const float* __restrict__ src,
                                       float* __restrict__ dst,
                                       const float* __restrict__ g,
                                       const float* __restrict__ be, int lane) {
    float4 vals[4];
    float s = 0.f, ss = 0.f;
#pragma unroll
    for (int t = 0; t < 4; t++) {
        vals[t] = *(const float4*)(src + lane * 4 + t * 128);
        s  += vals[t].x + vals[t].y + vals[t].z + vals[t].w;
        ss += vals[t].x*vals[t].x + vals[t].y*vals[t].y
            + vals[t].z*vals[t].z + vals[t].w*vals[t].w;
    }
#pragma unroll
    for (int o = 16; o; o >>= 1) {
        s  += __shfl_xor_sync(0xffffffffu, s,  o);
        ss += __shfl_xor_sync(0xffffffffu, ss, o);
    }
    float mean = s * (1.f / 512.f);
    float var  = ss * (1.f / 512.f) - mean * mean;
    float rstd = rsqrtf(var + 1e-6f);
#pragma unroll
    for (int t = 0; t < 4; t++) {
        int e = lane * 4 + t * 128;
        float4 o4;
        o4.x = (vals[t].x - mean) * rstd * g[e+0] + be[e+0];
        o4.y = (vals[t].y - mean) * rstd * g[e+1] + be[e+1];
        o4.z = (vals[t].z - mean) * rstd * g[e+2] + be[e+2];
        o4.w = (vals[t].w - mean) * rstd * g[e+3] + be[e+3];
        *(float4*)(dst + e) = o4;
    }
}

__global__ void ln_concat_k(const float* __restrict__ mem, const float* __restrict__ x,
                            const float* __restrict__ gam, const float* __restrict__ bet,
                            float* __restrict__ out, int l) {
    int row  = blockIdx.x * 8 + (threadIdx.x >> 5);
    int lane = threadIdx.x & 31;
    int b = row >> 10, j = row & 1023;
    const float* src = (j < MEM_)
        ? (mem + ((long)(b * MEM_ + j) * LL + l) * EE)
        : (x   +  (long)(b * SS + (j - MEM_)) * EE);
    ln_row(src, out + (long)row * EE, gam + l * EE, bet + l * EE, lane);
}

__global__ void ln_plain_k(const float* __restrict__ in,
                           const float* __restrict__ gam, const float* __restrict__ bet,
                           float* __restrict__ out, int l) {
    int row  = blockIdx.x * 8 + (threadIdx.x >> 5);
    int lane = threadIdx.x & 31;
    ln_row(in + (long)row * EE, out + (long)row * EE, gam + l * EE, bet + l * EE, lane);
}

// ---------------- masked rel-shift softmax (warp per row, in-place) ------------
__global__ __launch_bounds__(256)
void softmax_k(float* __restrict__ sc, const float* __restrict__ P) {
    long row = (long)blockIdx.x * 8 + (threadIdx.x >> 5);
    int lane = threadIdx.x & 31;
    int i = (int)(row & (SS - 1));
    int jmax = MEM_ + i;
    float* srow = sc + row * KK;
    const float* prow = P + row * KK + (SS - 1 - i);
    float v[32];
    float mx = -1e30f;
#pragma unroll
    for (int t = 0; t < 32; t++) {
        int j = t * 32 + lane;
        float x = -1e30f;
        if (j <= jmax) x = srow[j] + prow[j];
        v[t] = x;
        mx = fmaxf(mx, x);
    }
#pragma unroll
    for (int o = 16; o; o >>= 1) mx = fmaxf(mx, __shfl_xor_sync(0xffffffffu, mx, o));
    float s = 0.f;
#pragma unroll
    for (int t = 0; t < 32; t++) {
        float e = (v[t] > -1e29f) ? __expf(v[t] - mx) : 0.f;
        v[t] = e; s += e;
    }
#pragma unroll
    for (int o = 16; o; o >>= 1) s += __shfl_xor_sync(0xffffffffu, s, o);
    float inv = 1.f / s;
#pragma unroll
    for (int t = 0; t < 32; t++) srow[t * 32 + lane] = v[t] * inv;
}

// ---------------- host orchestration ------------------------------------------
extern "C" void kernel_launch(void* const* d_in, const int* in_sizes, int n_in,
                              void* d_out, int out_size) {
    (void)in_sizes; (void)n_in; (void)out_size;
    const float* obs    = (const float*)d_in[0];
    const float* mems   = (const float*)d_in[1];
    const float* W_enc  = (const float*)d_in[3];
    const float* b_enc  = (const float*)d_in[4];
    const float* ln1_s  = (const float*)d_in[5];
    const float* ln1_b  = (const float*)d_in[6];
    const float* Wq     = (const float*)d_in[7];
    const float* bq     = (const float*)d_in[8];
    const float* Wk     = (const float*)d_in[9];
    const float* bk     = (const float*)d_in[10];
    const float* Wv     = (const float*)d_in[11];
    const float* bv     = (const float*)d_in[12];
    const float* Wr     = (const float*)d_in[13];
    const float* ub     = (const float*)d_in[14];
    const float* vbias  = (const float*)d_in[15];
    const float* Wo     = (const float*)d_in[16];
    const float* bo     = (const float*)d_in[17];
    const float* ln2_s  = (const float*)d_in[18];
    const float* ln2_b  = (const float*)d_in[19];
    const float* W1     = (const float*)d_in[20];
    const float* b1     = (const float*)d_in[21];
    const float* W2     = (const float*)d_in[22];
    const float* b2     = (const float*)d_in[23];
    float* out = (float*)d_out;

    float *px, *ph, *phn, *pt, *pvk, *pq, *pk, *pv_, *po, *pr, *ppe, *psc, *pP;
    cudaGetSymbolAddress((void**)&px,  g_x);
    cudaGetSymbolAddress((void**)&ph,  g_h);
    cudaGetSymbolAddress((void**)&phn, g_hn);
    cudaGetSymbolAddress((void**)&pt,  g_t);
    cudaGetSymbolAddress((void**)&pvk, g_vk);
    cudaGetSymbolAddress((void**)&pq,  g_q);
    cudaGetSymbolAddress((void**)&pk,  g_k);
    cudaGetSymbolAddress((void**)&pv_, g_v);
    cudaGetSymbolAddress((void**)&po,  g_o);
    cudaGetSymbolAddress((void**)&pr,  g_r);
    cudaGetSymbolAddress((void**)&ppe, g_pe);
    cudaGetSymbolAddress((void**)&psc, g_sc);
    cudaGetSymbolAddress((void**)&pP,  g_P);

    cudaFuncSetAttribute(mma_gemm_cb<0>, cudaFuncAttributeMaxDynamicSharedMemorySize, CB_SMEM_BYTES);
    cudaFuncSetAttribute(mma_gemm_cb<1>, cudaFuncAttributeMaxDynamicSharedMemorySize, CB_SMEM_BYTES);
    cudaFuncSetAttribute(mma_gemm_cb<2>, cudaFuncAttributeMaxDynamicSharedMemorySize, CB_SMEM_BYTES);
    cudaFuncSetAttribute(mma_gemm_cb<3>, cudaFuncAttributeMaxDynamicSharedMemorySize, CB_SMEM_BYTES);
    cudaFuncSetAttribute(mma_gemm_ca<0>, cudaFuncAttributeMaxDynamicSharedMemorySize, CA_SMEM_BYTES);
    cudaFuncSetAttribute(mma_gemm_sc,    cudaFuncAttributeMaxDynamicSharedMemorySize, SMEM_BYTES);

    const long SE = (long)SS * EE, KE = (long)KK * EE, SK = (long)SS * KK;
    const long HSK = (long)HH * SK;

    // encoder: x = obs @ W_enc + b_enc
    mma_gemm_cb<1><<<dim3(4, 32, 1), 256, CB_SMEM_BYTES>>>(
        obs, 0, 0, OBS_, W_enc, 0, 0, EE, px, 0, 0, EE,
        b_enc, nullptr, 1, OBS_);
    pe_kernel<<<(KK * EE) / 256, 256>>>(ppe);

    for (int l = 0; l < LL; l++) {
        ln_concat_k<<<(BB * KK) / 8, 256>>>(mems, px, ln1_s, ln1_b, pvk, l);

        mma_gemm_cb<1><<<dim3(4, 64, 1), 256, CB_SMEM_BYTES>>>(
            pvk, 0, 0, EE, Wk + (long)l * LW, 0, 0, EE, pk, 0, 0, EE,
            bk + l * EE, nullptr, 1, EE);
        mma_gemm_cb<1><<<dim3(4, 64, 1), 256, CB_SMEM_BYTES>>>(
            pvk, 0, 0, EE, Wv + (long)l * LW, 0, 0, EE, pv_, 0, 0, EE,
            bv + l * EE, nullptr, 1, EE);
        mma_gemm_cb<1><<<dim3(4, 4, BB), 256, CB_SMEM_BYTES>>>(
            pvk + (long)MEM_ * EE, KE, 0, EE, Wq + (long)l * LW, 0, 0, EE,
            pq, SE, 0, EE, bq + l * EE, nullptr, 1, EE);
        mma_gemm_cb<0><<<dim3(4, 8, 1), 256, CB_SMEM_BYTES>>>(
            ppe, 0, 0, EE, Wr + (long)l * LW, 0, 0, EE, pr, 0, 0, EE,
            nullptr, nullptr, 1, EE);

        // AC = ((q+u)*0.125) @ k^T
        mma_gemm_sc<<<dim3(16, 4, BB*HH), 256, SMEM_BYTES>>>(
            pq, SE, DH_, EE, pk, KE, DH_, EE, psc, HSK, SK, KK,
            ub + (long)l * EE, HH, DH_);
        // P = ((q+v)*0.125) @ r^T
        mma_gemm_sc<<<dim3(16, 4, BB*HH), 256, SMEM_BYTES>>>(
            pq, SE, DH_, EE, pr, 0, DH_, EE, pP, HSK, SK, KK,
            vbias + (long)l * EE, HH, DH_);

        softmax_k<<<(BB * HH * SS) / 8, 256>>>(psc, pP);

        // o = probs @ v
        mma_gemm_ca<0><<<dim3(1, 4, BB*HH), 256, CA_SMEM_BYTES>>>(
            psc, HSK, SK, KK, pv_, KE, DH_, EE, po, SE, DH_, EE,
            nullptr, nullptr, HH, KK);

        mma_gemm_cb<3><<<dim3(4, 32, 1), 256, CB_SMEM_BYTES>>>(
            po, 0, 0, EE, Wo + (long)l * LW, 0, 0, EE, ph, 0, 0, EE,
            bo + l * EE, px, 1, EE);
        ln_plain_k<<<(BB * SS) / 8, 256>>>(ph, ln2_s, ln2_b, phn, l);
        mma_gemm_cb<2><<<dim3(4, 32, 1), 256, CB_SMEM_BYTES>>>(
            phn, 0, 0, EE, W1 + (long)l * LW, 0, 0, EE, pt, 0, 0, EE,
            b1 + l * EE, nullptr, 1, EE);
        float* xo = (l == LL - 1) ? out : px;
        mma_gemm_cb<3><<<dim3(4, 32, 1), 256, CB_SMEM_BYTES>>>(
            pt, 0, 0, EE, W2 + (long)l * LW, 0, 0, EE, xo, 0, 0, EE,
            b2 + l * EE, ph, 1, EE);
    }
}